// round 2
// baseline (speedup 1.0000x reference)
#include <cuda_runtime.h>

#define NB   64
#define ND   2048
#define NE   64
#define NH1  512
#define NH2  256
#define EPSB 1e-5f

// Scratch (allocation-free): precomputed per-call
__device__ float g_W1c[ND * NH1];          // W1d * c1   (4 MB)
__device__ float g_F[ND * NH1];            // emb_h * c1 (4 MB)
__device__ float g_G[NB * NH1];            // (rep@W1d + b1)*c1 + c0
__device__ float g_c1[NH1], g_c0[NH1];
__device__ float g_e1[NH2], g_e0[NH2], g_w3[NH2];

// ---------- packed f32x2 helpers (Blackwell FFMA2) ----------
__device__ __forceinline__ unsigned long long pack2same(float x) {
    unsigned long long r;
    asm("mov.b64 %0, {%1, %1};" : "=l"(r) : "f"(x));
    return r;
}
__device__ __forceinline__ unsigned long long ffma2(unsigned long long a,
                                                    unsigned long long b,
                                                    unsigned long long c) {
    unsigned long long d;
    asm("fma.rn.f32x2 %0, %1, %2, %3;" : "=l"(d) : "l"(a), "l"(b), "l"(c));
    return d;
}
__device__ __forceinline__ float2 unpack2(unsigned long long v) {
    float2 f;
    asm("mov.b64 {%0, %1}, %2;" : "=f"(f.x), "=f"(f.y) : "l"(v));
    return f;
}

// ---------- prep: fold BN constants ----------
__global__ void prep_consts(const float* __restrict__ g1, const float* __restrict__ beta1,
                            const float* __restrict__ m1, const float* __restrict__ v1,
                            const float* __restrict__ b2, const float* __restrict__ g2,
                            const float* __restrict__ beta2, const float* __restrict__ m2,
                            const float* __restrict__ v2, const float* __restrict__ W3) {
    int t = threadIdx.x;
    if (t < NH1) {
        float c1 = g1[t] * rsqrtf(v1[t] + EPSB);
        g_c1[t] = c1;
        g_c0[t] = beta1[t] - m1[t] * c1;
    }
    if (t < NH2) {
        float e1 = g2[t] * rsqrtf(v2[t] + EPSB);
        g_e1[t] = e1;
        g_e0[t] = (b2[t] - m2[t]) * e1 + beta2[t];
        g_w3[t] = W3[t];
    }
}

// ---------- prep: W1c[d,h] = W1[d,h] * c1[h] ----------
__global__ __launch_bounds__(256) void prep_W1c(const float* __restrict__ W1) {
    int i = blockIdx.x * 256 + threadIdx.x;      // float4 index
    float4 w = ((const float4*)W1)[i];
    int h = (i << 2) & (NH1 - 1);
    float4 c = *(const float4*)(g_c1 + h);
    float4 o;
    o.x = w.x * c.x; o.y = w.y * c.y; o.z = w.z * c.z; o.w = w.w * c.w;
    ((float4*)g_W1c)[i] = o;
}

// ---------- prep: F[k,h] = (emb @ W1e)[k,h] * c1[h] ----------
__global__ __launch_bounds__(512) void prep_F(const float* __restrict__ emb,
                                              const float* __restrict__ W1) {
    __shared__ float es[8 * NE];
    int kb = blockIdx.x * 8;
    for (int i = threadIdx.x; i < 8 * NE; i += 512) es[i] = emb[(size_t)kb * NE + i];
    __syncthreads();
    int h = threadIdx.x;
    const float* W1e = W1 + (size_t)ND * NH1;
    float acc[8];
#pragma unroll
    for (int kr = 0; kr < 8; kr++) acc[kr] = 0.f;
#pragma unroll 4
    for (int e = 0; e < NE; e++) {
        float w = W1e[(size_t)e * NH1 + h];
#pragma unroll
        for (int kr = 0; kr < 8; kr++) acc[kr] = fmaf(es[kr * NE + e], w, acc[kr]);
    }
    float c1h = g_c1[h];
#pragma unroll
    for (int kr = 0; kr < 8; kr++) g_F[(size_t)(kb + kr) * NH1 + h] = acc[kr] * c1h;
}

// ---------- prep: G[b,h] = ((rep@W1d)[b,h] + b1[h])*c1[h] + c0[h] ----------
// Grid: 32 CTAs, each owns a 16-wide h-slice for ALL b (W1 read exactly once total).
__global__ __launch_bounds__(256) void prep_G(const float* __restrict__ rep,
                                              const float* __restrict__ W1,
                                              const float* __restrict__ b1) {
    __shared__ float reps[64 * 132];   // pad 132 to spread banks
    int h = blockIdx.x * 16 + (threadIdx.x & 3) * 4;
    int b = threadIdx.x >> 2;
    float4 acc = {0.f, 0.f, 0.f, 0.f};
    for (int d0 = 0; d0 < ND; d0 += 128) {
        __syncthreads();
        for (int i = threadIdx.x; i < 64 * 128; i += 256) {
            int bb = i >> 7, dd = i & 127;
            reps[bb * 132 + dd] = rep[(size_t)bb * ND + d0 + dd];
        }
        __syncthreads();
        const float* rrow = reps + b * 132;
#pragma unroll 4
        for (int dd = 0; dd < 128; dd++) {
            float rv = rrow[dd];
            float4 w = *(const float4*)(W1 + (size_t)(d0 + dd) * NH1 + h);
            acc.x = fmaf(rv, w.x, acc.x);
            acc.y = fmaf(rv, w.y, acc.y);
            acc.z = fmaf(rv, w.z, acc.z);
            acc.w = fmaf(rv, w.w, acc.w);
        }
    }
    float4 bb = *(const float4*)(b1 + h);
    float4 c1 = *(const float4*)(g_c1 + h);
    float4 c0 = *(const float4*)(g_c0 + h);
    float4 o;
    o.x = fmaf(acc.x + bb.x, c1.x, c0.x);
    o.y = fmaf(acc.y + bb.y, c1.y, c0.y);
    o.z = fmaf(acc.z + bb.z, c1.z, c0.z);
    o.w = fmaf(acc.w + bb.w, c1.w, c0.w);
    *(float4*)(g_G + (size_t)b * NH1 + h) = o;
}

// ---------- main fused kernel ----------
// Grid: (D/64, B). Block: 256 threads (8 warps).
// CTA tile: M=64 rows (k), N=256 cols (o), K chunks of 32 (h).
// warp: rowgroup = warp&3 (16 rows), colgroup = warp>>2 (128 cols); lane: 4 cols.
// A stored row-pair-packed with XOR swizzle: As[h*64 + (k ^ (h&0x1C))].
__global__ __launch_bounds__(256, 2) void fused_main(
    const float* __restrict__ rep, const float* __restrict__ W2,
    const float* __restrict__ b3, float* __restrict__ out)
{
    __shared__ __align__(16) float As[32 * 64];    // 8 KB
    __shared__ __align__(16) float Bs[32 * 256];   // 32 KB
    __shared__ float reps[64];
    __shared__ float part[2][64];

    const int b  = blockIdx.y;
    const int k0 = blockIdx.x * 64;
    const int t  = threadIdx.x;
    const int warp = t >> 5, lane = t & 31;
    const int rowg = warp & 3, colg = warp >> 2;
    const int r0 = rowg * 16;
    const int c0 = colg * 128 + lane * 4;

    if (t < 64) reps[t] = rep[(size_t)b * ND + k0 + t];
    __syncthreads();

    unsigned long long acc[8][4];
#pragma unroll
    for (int i = 0; i < 8; i++)
#pragma unroll
        for (int j = 0; j < 4; j++) acc[i][j] = 0ULL;

    const float* Gb = g_G + (size_t)b * NH1;

#pragma unroll 1
    for (int h0 = 0; h0 < NH1; h0 += 32) {
        // -------- stage A: build h1f chunk (swizzled [h][k]) --------
#pragma unroll
        for (int r = 0; r < 2; r++) {
            int idx = t + r * 256;
            int k   = idx >> 3;            // 0..63
            int c4  = (idx & 7) << 2;      // 0,4,..,28
            size_t off = (size_t)(k0 + k) * NH1 + h0 + c4;
            float4 wv = *(const float4*)(g_W1c + off);
            float4 fv = *(const float4*)(g_F + off);
            float4 gv = *(const float4*)(Gb + h0 + c4);
            float rp = reps[k];
            int kp = k ^ c4;   // (c4+j)&0x1C == c4 for j<4
            As[(c4 + 0) * 64 + kp] = fmaxf(gv.x + fv.x - rp * wv.x, 0.f);
            As[(c4 + 1) * 64 + kp] = fmaxf(gv.y + fv.y - rp * wv.y, 0.f);
            As[(c4 + 2) * 64 + kp] = fmaxf(gv.z + fv.z - rp * wv.z, 0.f);
            As[(c4 + 3) * 64 + kp] = fmaxf(gv.w + fv.w - rp * wv.w, 0.f);
        }
        // -------- load W2 chunk into Bs --------
#pragma unroll
        for (int r = 0; r < 8; r++) {
            int idx = t + r * 256;
            int row = idx >> 6;
            int c   = (idx & 63) << 2;
            *(float4*)(Bs + row * 256 + c) =
                *(const float4*)(W2 + (size_t)(h0 + row) * NH2 + c);
        }
        __syncthreads();

        // -------- microkernel: 16 rows x 4 cols per thread, FFMA2 on row-pairs --------
#pragma unroll 8
        for (int kk = 0; kk < 32; kk++) {
            float4 bv = *(const float4*)(Bs + kk * 256 + c0);
            unsigned long long bd[4];
            bd[0] = pack2same(bv.x); bd[1] = pack2same(bv.y);
            bd[2] = pack2same(bv.z); bd[3] = pack2same(bv.w);
            const int s = kk & 0x1C;
            const float* arow = As + kk * 64;
#pragma unroll
            for (int i = 0; i < 4; i++) {
                ulonglong2 ap = *(const ulonglong2*)(arow + ((r0 + 4 * i) ^ s));
#pragma unroll
                for (int j = 0; j < 4; j++) {
                    acc[2 * i][j]     = ffma2(ap.x, bd[j], acc[2 * i][j]);
                    acc[2 * i + 1][j] = ffma2(ap.y, bd[j], acc[2 * i + 1][j]);
                }
            }
        }
        __syncthreads();
    }

    // -------- epilogue: BN2+relu, dot W3, reduce over cols --------
    float e1v[4], e0v[4], w3v[4];
#pragma unroll
    for (int j = 0; j < 4; j++) {
        e1v[j] = g_e1[c0 + j];
        e0v[j] = g_e0[c0 + j];
        w3v[j] = g_w3[c0 + j];
    }

#pragma unroll
    for (int p = 0; p < 8; p++) {   // row pair p -> rows r0+2p, r0+2p+1
        float se = 0.f, so = 0.f;
#pragma unroll
        for (int j = 0; j < 4; j++) {
            float2 v = unpack2(acc[p][j]);
            se = fmaf(fmaxf(fmaf(v.x, e1v[j], e0v[j]), 0.f), w3v[j], se);
            so = fmaf(fmaxf(fmaf(v.y, e1v[j], e0v[j]), 0.f), w3v[j], so);
        }
#pragma unroll
        for (int off = 16; off; off >>= 1) {
            se += __shfl_xor_sync(0xffffffffu, se, off);
            so += __shfl_xor_sync(0xffffffffu, so, off);
        }
        if (lane == 0) {
            part[colg][r0 + 2 * p]     = se;
            part[colg][r0 + 2 * p + 1] = so;
        }
    }
    __syncthreads();
    if (t < 64) out[(size_t)b * ND + k0 + t] = part[0][t] + part[1][t] + b3[0];
}

extern "C" void kernel_launch(void* const* d_in, const int* in_sizes, int n_in,
                              void* d_out, int out_size) {
    const float* rep   = (const float*)d_in[0];
    const float* emb   = (const float*)d_in[1];
    const float* W1    = (const float*)d_in[2];
    const float* b1    = (const float*)d_in[3];
    const float* g1    = (const float*)d_in[4];
    const float* beta1 = (const float*)d_in[5];
    const float* m1    = (const float*)d_in[6];
    const float* v1    = (const float*)d_in[7];
    const float* W2    = (const float*)d_in[8];
    const float* b2    = (const float*)d_in[9];
    const float* g2    = (const float*)d_in[10];
    const float* beta2 = (const float*)d_in[11];
    const float* m2    = (const float*)d_in[12];
    const float* v2    = (const float*)d_in[13];
    const float* W3    = (const float*)d_in[14];
    const float* b3    = (const float*)d_in[15];
    float* out = (float*)d_out;

    prep_consts<<<1, 512>>>(g1, beta1, m1, v1, b2, g2, beta2, m2, v2, W3);
    prep_W1c<<<(ND * NH1 / 4) / 256, 256>>>(W1);
    prep_F<<<ND / 8, 512>>>(emb, W1);
    prep_G<<<NH1 / 16, 256>>>(rep, W1, b1);
    dim3 grid(ND / 64, NB);
    fused_main<<<grid, 256>>>(rep, W2, b3, out);
}

// round 3
// speedup vs baseline: 1.1521x; 1.1521x over previous
#include <cuda_runtime.h>

#define NB   64
#define ND   2048
#define NE   64
#define NH1  512
#define NH2  256
#define EPSB 1e-5f

// Scratch (allocation-free): precomputed per-call
__device__ float g_W1c[ND * NH1];          // W1d * c1   (4 MB)
__device__ float g_F[ND * NH1];            // emb_h * c1 (4 MB)
__device__ float g_Gp[4 * NB * NH1];       // split-D partials of rep@W1d
__device__ float g_G[NB * NH1];            // ((rep@W1d)+b1)*c1 + c0
__device__ float g_c1[NH1], g_c0[NH1];
__device__ float g_e1[NH2], g_e0[NH2], g_w3[NH2];

// ---------- packed f32x2 helpers (Blackwell FFMA2) ----------
__device__ __forceinline__ unsigned long long pack2same(float x) {
    unsigned long long r;
    asm("mov.b64 %0, {%1, %1};" : "=l"(r) : "f"(x));
    return r;
}
__device__ __forceinline__ unsigned long long ffma2(unsigned long long a,
                                                    unsigned long long b,
                                                    unsigned long long c) {
    unsigned long long d;
    asm("fma.rn.f32x2 %0, %1, %2, %3;" : "=l"(d) : "l"(a), "l"(b), "l"(c));
    return d;
}
__device__ __forceinline__ float2 unpack2(unsigned long long v) {
    float2 f;
    asm("mov.b64 {%0, %1}, %2;" : "=f"(f.x), "=f"(f.y) : "l"(v));
    return f;
}

// ---------- prep: fold BN constants ----------
__global__ void prep_consts(const float* __restrict__ g1, const float* __restrict__ beta1,
                            const float* __restrict__ m1, const float* __restrict__ v1,
                            const float* __restrict__ b2, const float* __restrict__ g2,
                            const float* __restrict__ beta2, const float* __restrict__ m2,
                            const float* __restrict__ v2, const float* __restrict__ W3) {
    int t = threadIdx.x;
    if (t < NH1) {
        float c1 = g1[t] * rsqrtf(v1[t] + EPSB);
        g_c1[t] = c1;
        g_c0[t] = beta1[t] - m1[t] * c1;
    }
    if (t < NH2) {
        float e1 = g2[t] * rsqrtf(v2[t] + EPSB);
        g_e1[t] = e1;
        g_e0[t] = (b2[t] - m2[t]) * e1 + beta2[t];
        g_w3[t] = W3[t];
    }
}

// ---------- prep: W1c[d,h] = W1[d,h] * c1[h] ----------
__global__ __launch_bounds__(256) void prep_W1c(const float* __restrict__ W1) {
    int i = blockIdx.x * 256 + threadIdx.x;      // float4 index
    float4 w = ((const float4*)W1)[i];
    int h = (i << 2) & (NH1 - 1);
    float4 c = *(const float4*)(g_c1 + h);
    float4 o;
    o.x = w.x * c.x; o.y = w.y * c.y; o.z = w.z * c.z; o.w = w.w * c.w;
    ((float4*)g_W1c)[i] = o;
}

// ---------- prep: F[k,h] = (emb @ W1e)[k,h] * c1[h] ----------
__global__ __launch_bounds__(512) void prep_F(const float* __restrict__ emb,
                                              const float* __restrict__ W1) {
    __shared__ float es[8 * NE];
    int kb = blockIdx.x * 8;
    for (int i = threadIdx.x; i < 8 * NE; i += 512) es[i] = emb[(size_t)kb * NE + i];
    __syncthreads();
    int h = threadIdx.x;
    const float* W1e = W1 + (size_t)ND * NH1;
    float acc[8];
#pragma unroll
    for (int kr = 0; kr < 8; kr++) acc[kr] = 0.f;
#pragma unroll 4
    for (int e = 0; e < NE; e++) {
        float w = W1e[(size_t)e * NH1 + h];
#pragma unroll
        for (int kr = 0; kr < 8; kr++) acc[kr] = fmaf(es[kr * NE + e], w, acc[kr]);
    }
    float c1h = g_c1[h];
#pragma unroll
    for (int kr = 0; kr < 8; kr++) g_F[(size_t)(kb + kr) * NH1 + h] = acc[kr] * c1h;
}

// ---------- prep: split-D partials of base = rep @ W1d ----------
// Grid: (NB, 4). Each CTA: b = blockIdx.x, d-slice = blockIdx.y (512 wide).
// 512 threads, one h each; W1 reads coalesced (2 KB/iter), L2-resident.
__global__ __launch_bounds__(512) void prep_base_partial(const float* __restrict__ rep,
                                                         const float* __restrict__ W1) {
    __shared__ float reps[512];
    const int b  = blockIdx.x;
    const int d0 = blockIdx.y * 512;
    const int h  = threadIdx.x;
    reps[h] = rep[(size_t)b * ND + d0 + h];
    __syncthreads();
    float acc = 0.f;
    const float* Wp = W1 + (size_t)d0 * NH1 + h;
#pragma unroll 8
    for (int d = 0; d < 512; d++)
        acc = fmaf(reps[d], Wp[(size_t)d * NH1], acc);
    g_Gp[((size_t)blockIdx.y * NB + b) * NH1 + h] = acc;
}

// ---------- prep: fold partials -> G ----------
__global__ __launch_bounds__(512) void prep_G_fold(const float* __restrict__ b1) {
    const int b = blockIdx.x;
    const int h = threadIdx.x;
    float s = g_Gp[((size_t)0 * NB + b) * NH1 + h]
            + g_Gp[((size_t)1 * NB + b) * NH1 + h]
            + g_Gp[((size_t)2 * NB + b) * NH1 + h]
            + g_Gp[((size_t)3 * NB + b) * NH1 + h];
    g_G[(size_t)b * NH1 + h] = fmaf(s + b1[h], g_c1[h], g_c0[h]);
}

// ---------- main fused kernel ----------
// Grid: (D/64, B). Block: 256 threads (8 warps).
// CTA tile: M=64 rows (k), N=256 cols (o), K chunks of 32 (h).
// warp: rowgroup = warp&3 (16 rows), colgroup = warp>>2 (128 cols); lane: 4 cols.
// A stored row-pair-packed with XOR swizzle: As[h*64 + (k ^ (h&0x1C))].
__global__ __launch_bounds__(256, 2) void fused_main(
    const float* __restrict__ rep, const float* __restrict__ W2,
    const float* __restrict__ b3, float* __restrict__ out)
{
    __shared__ __align__(16) float As[32 * 64];    // 8 KB
    __shared__ __align__(16) float Bs[32 * 256];   // 32 KB
    __shared__ float reps[64];
    __shared__ float part[2][64];

    const int b  = blockIdx.y;
    const int k0 = blockIdx.x * 64;
    const int t  = threadIdx.x;
    const int warp = t >> 5, lane = t & 31;
    const int rowg = warp & 3, colg = warp >> 2;
    const int r0 = rowg * 16;
    const int c0 = colg * 128 + lane * 4;

    if (t < 64) reps[t] = rep[(size_t)b * ND + k0 + t];
    __syncthreads();

    unsigned long long acc[8][4];
#pragma unroll
    for (int i = 0; i < 8; i++)
#pragma unroll
        for (int j = 0; j < 4; j++) acc[i][j] = 0ULL;

    const float* Gb = g_G + (size_t)b * NH1;

#pragma unroll 1
    for (int h0 = 0; h0 < NH1; h0 += 32) {
        // -------- stage A: build h1f chunk (swizzled [h][k]) --------
#pragma unroll
        for (int r = 0; r < 2; r++) {
            int idx = t + r * 256;
            int k   = idx >> 3;            // 0..63
            int c4  = (idx & 7) << 2;      // 0,4,..,28
            size_t off = (size_t)(k0 + k) * NH1 + h0 + c4;
            float4 wv = *(const float4*)(g_W1c + off);
            float4 fv = *(const float4*)(g_F + off);
            float4 gv = *(const float4*)(Gb + h0 + c4);
            float rp = reps[k];
            int kp = k ^ c4;   // (c4+j)&0x1C == c4 for j<4
            As[(c4 + 0) * 64 + kp] = fmaxf(gv.x + fv.x - rp * wv.x, 0.f);
            As[(c4 + 1) * 64 + kp] = fmaxf(gv.y + fv.y - rp * wv.y, 0.f);
            As[(c4 + 2) * 64 + kp] = fmaxf(gv.z + fv.z - rp * wv.z, 0.f);
            As[(c4 + 3) * 64 + kp] = fmaxf(gv.w + fv.w - rp * wv.w, 0.f);
        }
        // -------- load W2 chunk into Bs --------
#pragma unroll
        for (int r = 0; r < 8; r++) {
            int idx = t + r * 256;
            int row = idx >> 6;
            int c   = (idx & 63) << 2;
            *(float4*)(Bs + row * 256 + c) =
                *(const float4*)(W2 + (size_t)(h0 + row) * NH2 + c);
        }
        __syncthreads();

        // -------- microkernel: 16 rows x 4 cols per thread, FFMA2 on row-pairs --------
#pragma unroll 8
        for (int kk = 0; kk < 32; kk++) {
            float4 bv = *(const float4*)(Bs + kk * 256 + c0);
            unsigned long long bd[4];
            bd[0] = pack2same(bv.x); bd[1] = pack2same(bv.y);
            bd[2] = pack2same(bv.z); bd[3] = pack2same(bv.w);
            const int s = kk & 0x1C;
            const float* arow = As + kk * 64;
#pragma unroll
            for (int i = 0; i < 4; i++) {
                ulonglong2 ap = *(const ulonglong2*)(arow + ((r0 + 4 * i) ^ s));
#pragma unroll
                for (int j = 0; j < 4; j++) {
                    acc[2 * i][j]     = ffma2(ap.x, bd[j], acc[2 * i][j]);
                    acc[2 * i + 1][j] = ffma2(ap.y, bd[j], acc[2 * i + 1][j]);
                }
            }
        }
        __syncthreads();
    }

    // -------- epilogue: BN2+relu, dot W3, reduce over cols --------
    float e1v[4], e0v[4], w3v[4];
#pragma unroll
    for (int j = 0; j < 4; j++) {
        e1v[j] = g_e1[c0 + j];
        e0v[j] = g_e0[c0 + j];
        w3v[j] = g_w3[c0 + j];
    }

#pragma unroll
    for (int p = 0; p < 8; p++) {   // row pair p -> rows r0+2p, r0+2p+1
        float se = 0.f, so = 0.f;
#pragma unroll
        for (int j = 0; j < 4; j++) {
            float2 v = unpack2(acc[p][j]);
            se = fmaf(fmaxf(fmaf(v.x, e1v[j], e0v[j]), 0.f), w3v[j], se);
            so = fmaf(fmaxf(fmaf(v.y, e1v[j], e0v[j]), 0.f), w3v[j], so);
        }
#pragma unroll
        for (int off = 16; off; off >>= 1) {
            se += __shfl_xor_sync(0xffffffffu, se, off);
            so += __shfl_xor_sync(0xffffffffu, so, off);
        }
        if (lane == 0) {
            part[colg][r0 + 2 * p]     = se;
            part[colg][r0 + 2 * p + 1] = so;
        }
    }
    __syncthreads();
    if (t < 64) out[(size_t)b * ND + k0 + t] = part[0][t] + part[1][t] + b3[0];
}

extern "C" void kernel_launch(void* const* d_in, const int* in_sizes, int n_in,
                              void* d_out, int out_size) {
    const float* rep   = (const float*)d_in[0];
    const float* emb   = (const float*)d_in[1];
    const float* W1    = (const float*)d_in[2];
    const float* b1    = (const float*)d_in[3];
    const float* g1    = (const float*)d_in[4];
    const float* beta1 = (const float*)d_in[5];
    const float* m1    = (const float*)d_in[6];
    const float* v1    = (const float*)d_in[7];
    const float* W2    = (const float*)d_in[8];
    const float* b2    = (const float*)d_in[9];
    const float* g2    = (const float*)d_in[10];
    const float* beta2 = (const float*)d_in[11];
    const float* m2    = (const float*)d_in[12];
    const float* v2    = (const float*)d_in[13];
    const float* W3    = (const float*)d_in[14];
    const float* b3    = (const float*)d_in[15];
    float* out = (float*)d_out;

    prep_consts<<<1, 512>>>(g1, beta1, m1, v1, b2, g2, beta2, m2, v2, W3);
    prep_W1c<<<(ND * NH1 / 4) / 256, 256>>>(W1);
    prep_F<<<ND / 8, 512>>>(emb, W1);
    dim3 gbp(NB, 4);
    prep_base_partial<<<gbp, 512>>>(rep, W1);
    prep_G_fold<<<NB, 512>>>(b1);
    dim3 grid(ND / 64, NB);
    fused_main<<<grid, 256>>>(rep, W2, b3, out);
}

// round 5
// speedup vs baseline: 1.6057x; 1.3937x over previous
#include <cuda_runtime.h>
#include <cuda_bf16.h>
#include <cstdint>

#define NB   64
#define ND   2048
#define NE   64
#define NH1  512
#define NH2  256
#define EPSB 1e-5f

// Scratch (allocation-free)
__device__ float g_W1c[ND * NH1];              // W1d * c1   (4 MB)
__device__ float g_F[ND * NH1];                // emb_h * c1 (4 MB)
__device__ float g_Gp[4 * NB * NH1];
__device__ float g_G[NB * NH1];                // ((rep@W1d)+b1)*c1 + c0
__device__ float g_c1[NH1], g_c0[NH1];
__device__ float g_e1[NH2], g_e0[NH2], g_w3[NH2];
__device__ __nv_bfloat16 g_W2t_hi[NH2 * NH1];  // W2^T hi  [o][h]
__device__ __nv_bfloat16 g_W2t_lo[NH2 * NH1];  // W2^T lo  [o][h]

// ===================== helpers =====================
__device__ __forceinline__ uint32_t smem_u32(const void* p) {
    uint32_t a;
    asm("{ .reg .u64 t; cvta.to.shared.u64 t, %1; cvt.u32.u64 %0, t; }" : "=r"(a) : "l"(p));
    return a;
}
__device__ __forceinline__ void ldsm_x4(uint32_t* r, uint32_t addr) {
    asm volatile("ldmatrix.sync.aligned.m8n8.x4.shared.b16 {%0,%1,%2,%3}, [%4];"
                 : "=r"(r[0]), "=r"(r[1]), "=r"(r[2]), "=r"(r[3]) : "r"(addr));
}
__device__ __forceinline__ void mma_bf16(float* d, const uint32_t* a, const uint32_t* b) {
    asm volatile("mma.sync.aligned.m16n8k16.row.col.f32.bf16.bf16.f32 "
                 "{%0,%1,%2,%3}, {%4,%5,%6,%7}, {%8,%9}, {%0,%1,%2,%3};"
                 : "+f"(d[0]), "+f"(d[1]), "+f"(d[2]), "+f"(d[3])
                 : "r"(a[0]), "r"(a[1]), "r"(a[2]), "r"(a[3]), "r"(b[0]), "r"(b[1]));
}
#define SWZ(x) ((x) ^ (((x) >> 3) & 0x70))

// ===================== prep kernels =====================
__global__ void prep_consts(const float* __restrict__ g1, const float* __restrict__ beta1,
                            const float* __restrict__ m1, const float* __restrict__ v1,
                            const float* __restrict__ b2, const float* __restrict__ g2,
                            const float* __restrict__ beta2, const float* __restrict__ m2,
                            const float* __restrict__ v2, const float* __restrict__ W3) {
    int t = threadIdx.x;
    if (t < NH1) {
        float c1 = g1[t] * rsqrtf(v1[t] + EPSB);
        g_c1[t] = c1;
        g_c0[t] = beta1[t] - m1[t] * c1;
    }
    if (t < NH2) {
        float e1 = g2[t] * rsqrtf(v2[t] + EPSB);
        g_e1[t] = e1;
        g_e0[t] = (b2[t] - m2[t]) * e1 + beta2[t];
        g_w3[t] = W3[t];
    }
}

__global__ __launch_bounds__(256) void prep_W1c(const float* __restrict__ W1) {
    int i = blockIdx.x * 256 + threadIdx.x;
    float4 w = ((const float4*)W1)[i];
    int h = (i << 2) & (NH1 - 1);
    float4 c = *(const float4*)(g_c1 + h);
    float4 o;
    o.x = w.x * c.x; o.y = w.y * c.y; o.z = w.z * c.z; o.w = w.w * c.w;
    ((float4*)g_W1c)[i] = o;
}

__global__ __launch_bounds__(512) void prep_F(const float* __restrict__ emb,
                                              const float* __restrict__ W1) {
    __shared__ float es[8 * NE];
    int kb = blockIdx.x * 8;
    for (int i = threadIdx.x; i < 8 * NE; i += 512) es[i] = emb[(size_t)kb * NE + i];
    __syncthreads();
    int h = threadIdx.x;
    const float* W1e = W1 + (size_t)ND * NH1;
    float acc[8];
#pragma unroll
    for (int kr = 0; kr < 8; kr++) acc[kr] = 0.f;
#pragma unroll 4
    for (int e = 0; e < NE; e++) {
        float w = W1e[(size_t)e * NH1 + h];
#pragma unroll
        for (int kr = 0; kr < 8; kr++) acc[kr] = fmaf(es[kr * NE + e], w, acc[kr]);
    }
    float c1h = g_c1[h];
#pragma unroll
    for (int kr = 0; kr < 8; kr++) g_F[(size_t)(kb + kr) * NH1 + h] = acc[kr] * c1h;
}

__global__ __launch_bounds__(512) void prep_base_partial(const float* __restrict__ rep,
                                                         const float* __restrict__ W1) {
    __shared__ float reps[512];
    const int b  = blockIdx.x;
    const int d0 = blockIdx.y * 512;
    const int h  = threadIdx.x;
    reps[h] = rep[(size_t)b * ND + d0 + h];
    __syncthreads();
    float acc = 0.f;
    const float* Wp = W1 + (size_t)d0 * NH1 + h;
#pragma unroll 8
    for (int d = 0; d < 512; d++)
        acc = fmaf(reps[d], Wp[(size_t)d * NH1], acc);
    g_Gp[((size_t)blockIdx.y * NB + b) * NH1 + h] = acc;
}

__global__ __launch_bounds__(512) void prep_G_fold(const float* __restrict__ b1) {
    const int b = blockIdx.x;
    const int h = threadIdx.x;
    float s = g_Gp[((size_t)0 * NB + b) * NH1 + h]
            + g_Gp[((size_t)1 * NB + b) * NH1 + h]
            + g_Gp[((size_t)2 * NB + b) * NH1 + h]
            + g_Gp[((size_t)3 * NB + b) * NH1 + h];
    g_G[(size_t)b * NH1 + h] = fmaf(s + b1[h], g_c1[h], g_c0[h]);
}

// W2t[o][h] = split-bf16 of W2[h][o]
__global__ __launch_bounds__(256) void prep_W2t(const float* __restrict__ W2) {
    __shared__ float tile[32][33];
    int h0 = blockIdx.x * 32, o0 = blockIdx.y * 32;
    int tx = threadIdx.x & 31, ty = threadIdx.x >> 5;
#pragma unroll
    for (int r = 0; r < 4; r++)
        tile[ty + 8 * r][tx] = W2[(size_t)(h0 + ty + 8 * r) * NH2 + o0 + tx];
    __syncthreads();
#pragma unroll
    for (int r = 0; r < 4; r++) {
        int o = o0 + ty + 8 * r;
        int h = h0 + tx;
        float v = tile[tx][ty + 8 * r];
        __nv_bfloat16 hi = __float2bfloat16_rn(v);
        __nv_bfloat16 lo = __float2bfloat16_rn(v - __bfloat162float(hi));
        g_W2t_hi[(size_t)o * NH1 + h] = hi;
        g_W2t_lo[(size_t)o * NH1 + h] = lo;
    }
}

__global__ __launch_bounds__(256) void init_out(float* __restrict__ out,
                                                const float* __restrict__ b3) {
    int i = blockIdx.x * 256 + threadIdx.x;
    float v = b3[0];
    float4 o = {v, v, v, v};
    ((float4*)out)[i] = o;
}

// ===================== main HMMA kernel =====================
// Grid: (ND/128, NH2/128, NB). 256 threads (8 warps).
// CTA: M=128 k-rows, N=128 o-cols, K=512 in 8 chunks of 64.
// warps: rowg = wid>>2 (m64), colg = wid&3 (n32). 3-term split-bf16.
#define SM_E1    0          // 128 f
#define SM_E0    512
#define SM_W3    1024
#define SM_G     1536       // 512 f -> ends 3584
#define SM_REPS  3584       // 128 f -> 4096
#define SM_PART  4096       // 4*128 f -> 6144
#define SM_AHI   8192       // 16 KB
#define SM_ALO   24576      // 16 KB
#define SM_BHI   40960      // 16 KB
#define SM_BLO   57344      // 16 KB
#define SM_TOTAL 73728

__global__ __launch_bounds__(256, 2) void fused_mma(
    const float* __restrict__ rep, float* __restrict__ out)
{
    extern __shared__ __align__(1024) char smem[];
    const uint32_t sb = smem_u32(smem);
    const int b     = blockIdx.z;
    const int k0    = blockIdx.x * 128;
    const int ntile = blockIdx.y;          // 0 or 1 (o-half)
    const int t  = threadIdx.x;
    const int wid = t >> 5, lane = t & 31;
    const int rowg = wid >> 2, colg = wid & 3;

    // stage constants
    if (t < 128) {
        *(float*)(smem + SM_E1 + t * 4)   = g_e1[ntile * 128 + t];
        *(float*)(smem + SM_E0 + t * 4)   = g_e0[ntile * 128 + t];
        *(float*)(smem + SM_W3 + t * 4)   = g_w3[ntile * 128 + t];
        *(float*)(smem + SM_REPS + t * 4) = rep[(size_t)b * ND + k0 + t];
    }
    *(float*)(smem + SM_G + t * 4)         = g_G[(size_t)b * NH1 + t];
    *(float*)(smem + SM_G + (t + 256) * 4) = g_G[(size_t)b * NH1 + t + 256];
    if (t < 128) {
        *(float*)(smem + SM_PART + t * 4)         = 0.f;
        *(float*)(smem + SM_PART + (t + 128) * 4) = 0.f;
        *(float*)(smem + SM_PART + (t + 256) * 4) = 0.f;
        *(float*)(smem + SM_PART + (t + 384) * 4) = 0.f;
    }
    __syncthreads();

    // ldmatrix address precompute (byte offsets within 16KB tiles, SW128)
    uint32_t aOff[4]; int aXor[4];
#pragma unroll
    for (int mt = 0; mt < 4; mt++) {
        int rowA = rowg * 64 + mt * 16 + (lane & 15);
        aOff[mt] = rowA * 128;
        aXor[mt] = (rowA & 7) << 4;
    }
    const int aColSel = (lane & 16);           // 0 or 16 bytes
    uint32_t bOff[2]; int bXor[2];
#pragma unroll
    for (int bt = 0; bt < 2; bt++) {
        int rowB = colg * 32 + bt * 16 + (lane & 7) + ((lane & 16) >> 1);
        bOff[bt] = rowB * 128;
        bXor[bt] = (rowB & 7) << 4;
    }
    const int bColSel = (lane & 8) << 1;       // 0 or 16 bytes

    float D[4][4][4];
#pragma unroll
    for (int mt = 0; mt < 4; mt++)
#pragma unroll
        for (int nt = 0; nt < 4; nt++)
#pragma unroll
            for (int j = 0; j < 4; j++) D[mt][nt][j] = 0.f;

    const int krow = t >> 1;            // 0..127 (A build row)
    const int hl0  = (t & 1) * 32;
    const float rp = *(const float*)(smem + SM_REPS + krow * 4);

#pragma unroll 1
    for (int ch = 0; ch < 8; ch++) {
        const int h0 = ch * 64;
        // ---- build A_hi / A_lo (128 x 64 bf16, SW128) ----
#pragma unroll
        for (int j8 = 0; j8 < 8; j8++) {
            int h4 = hl0 + j8 * 4;
            size_t goff = (size_t)(k0 + krow) * NH1 + h0 + h4;
            float4 wv = *(const float4*)(g_W1c + goff);
            float4 fv = *(const float4*)(g_F + goff);
            float4 gv = *(const float4*)(smem + SM_G + (h0 + h4) * 4);
            float u0 = fmaxf(gv.x + fv.x - rp * wv.x, 0.f);
            float u1 = fmaxf(gv.y + fv.y - rp * wv.y, 0.f);
            float u2 = fmaxf(gv.z + fv.z - rp * wv.z, 0.f);
            float u3 = fmaxf(gv.w + fv.w - rp * wv.w, 0.f);
            __nv_bfloat16 h0b = __float2bfloat16_rn(u0);
            __nv_bfloat16 h1b = __float2bfloat16_rn(u1);
            __nv_bfloat16 h2b = __float2bfloat16_rn(u2);
            __nv_bfloat16 h3b = __float2bfloat16_rn(u3);
            __nv_bfloat16 l0b = __float2bfloat16_rn(u0 - __bfloat162float(h0b));
            __nv_bfloat16 l1b = __float2bfloat16_rn(u1 - __bfloat162float(h1b));
            __nv_bfloat16 l2b = __float2bfloat16_rn(u2 - __bfloat162float(h2b));
            __nv_bfloat16 l3b = __float2bfloat16_rn(u3 - __bfloat162float(h3b));
            uint32_t boff = SWZ(krow * 128 + h4 * 2);
            uint2 hv, lv;
            hv.x = ((uint32_t)__bfloat16_as_ushort(h1b) << 16) | __bfloat16_as_ushort(h0b);
            hv.y = ((uint32_t)__bfloat16_as_ushort(h3b) << 16) | __bfloat16_as_ushort(h2b);
            lv.x = ((uint32_t)__bfloat16_as_ushort(l1b) << 16) | __bfloat16_as_ushort(l0b);
            lv.y = ((uint32_t)__bfloat16_as_ushort(l3b) << 16) | __bfloat16_as_ushort(l2b);
            *(uint2*)(smem + SM_AHI + boff) = hv;
            *(uint2*)(smem + SM_ALO + boff) = lv;
        }
        // ---- load B_hi / B_lo chunk (128 o-rows x 64 h, SW128) ----
#pragma unroll
        for (int r = 0; r < 4; r++) {
            int idx = t + r * 256;          // 0..1023
            int row = idx >> 3;             // 0..127
            int seg = idx & 7;
            size_t go = (size_t)(ntile * 128 + row) * NH1 + h0 + seg * 8;
            uint32_t boff = SWZ(row * 128 + seg * 16);
            *(uint4*)(smem + SM_BHI + boff) = *(const uint4*)(g_W2t_hi + go);
            *(uint4*)(smem + SM_BLO + boff) = *(const uint4*)(g_W2t_lo + go);
        }
        __syncthreads();

        // ---- 4 k-steps of 16; 3 MMA terms each ----
#pragma unroll
        for (int ks = 0; ks < 4; ks++) {
            const int colA = ks * 32 + aColSel;
            const int colB = ks * 32 + bColSel;
            uint32_t ah[4][4], al[4][4], bf[2][4];
#pragma unroll
            for (int mt = 0; mt < 4; mt++) {
                ldsm_x4(ah[mt], sb + SM_AHI + aOff[mt] + (colA ^ aXor[mt]));
                ldsm_x4(al[mt], sb + SM_ALO + aOff[mt] + (colA ^ aXor[mt]));
            }
#pragma unroll
            for (int bt = 0; bt < 2; bt++)
                ldsm_x4(bf[bt], sb + SM_BHI + bOff[bt] + (colB ^ bXor[bt]));
#pragma unroll
            for (int mt = 0; mt < 4; mt++)
#pragma unroll
                for (int bt = 0; bt < 2; bt++) {
                    mma_bf16(D[mt][2 * bt],     ah[mt], bf[bt]);
                    mma_bf16(D[mt][2 * bt + 1], ah[mt], bf[bt] + 2);
                    mma_bf16(D[mt][2 * bt],     al[mt], bf[bt]);
                    mma_bf16(D[mt][2 * bt + 1], al[mt], bf[bt] + 2);
                }
#pragma unroll
            for (int bt = 0; bt < 2; bt++)
                ldsm_x4(bf[bt], sb + SM_BLO + bOff[bt] + (colB ^ bXor[bt]));
#pragma unroll
            for (int mt = 0; mt < 4; mt++)
#pragma unroll
                for (int bt = 0; bt < 2; bt++) {
                    mma_bf16(D[mt][2 * bt],     ah[mt], bf[bt]);
                    mma_bf16(D[mt][2 * bt + 1], ah[mt], bf[bt] + 2);
                }
        }
        __syncthreads();
    }

    // ---- epilogue: BN2 + relu + W3 dot, reduce over o ----
#pragma unroll
    for (int mt = 0; mt < 4; mt++) {
        int rbase = rowg * 64 + mt * 16 + (lane >> 2);
        float s0 = 0.f, s1 = 0.f;
#pragma unroll
        for (int nt = 0; nt < 4; nt++) {
#pragma unroll
            for (int j = 0; j < 2; j++) {
                int o = colg * 32 + nt * 8 + 2 * (lane & 3) + j;
                float e1 = *(const float*)(smem + SM_E1 + o * 4);
                float e0 = *(const float*)(smem + SM_E0 + o * 4);
                float w3 = *(const float*)(smem + SM_W3 + o * 4);
                s0 = fmaf(fmaxf(fmaf(D[mt][nt][j],     e1, e0), 0.f), w3, s0);
                s1 = fmaf(fmaxf(fmaf(D[mt][nt][2 + j], e1, e0), 0.f), w3, s1);
            }
        }
        s0 += __shfl_xor_sync(0xffffffffu, s0, 1);
        s0 += __shfl_xor_sync(0xffffffffu, s0, 2);
        s1 += __shfl_xor_sync(0xffffffffu, s1, 1);
        s1 += __shfl_xor_sync(0xffffffffu, s1, 2);
        if ((lane & 3) == 0) {
            *(float*)(smem + SM_PART + (colg * 128 + rbase) * 4)     = s0;
            *(float*)(smem + SM_PART + (colg * 128 + rbase + 8) * 4) = s1;
        }
    }
    __syncthreads();
    if (t < 128) {
        float v = *(const float*)(smem + SM_PART + t * 4)
                + *(const float*)(smem + SM_PART + (128 + t) * 4)
                + *(const float*)(smem + SM_PART + (256 + t) * 4)
                + *(const float*)(smem + SM_PART + (384 + t) * 4);
        atomicAdd(&out[(size_t)b * ND + k0 + t], v);
    }
}

extern "C" void kernel_launch(void* const* d_in, const int* in_sizes, int n_in,
                              void* d_out, int out_size) {
    const float* rep   = (const float*)d_in[0];
    const float* emb   = (const float*)d_in[1];
    const float* W1    = (const float*)d_in[2];
    const float* b1    = (const float*)d_in[3];
    const float* g1    = (const float*)d_in[4];
    const float* beta1 = (const float*)d_in[5];
    const float* m1    = (const float*)d_in[6];
    const float* v1    = (const float*)d_in[7];
    const float* W2    = (const float*)d_in[8];
    const float* b2    = (const float*)d_in[9];
    const float* g2    = (const float*)d_in[10];
    const float* beta2 = (const float*)d_in[11];
    const float* m2    = (const float*)d_in[12];
    const float* v2    = (const float*)d_in[13];
    const float* W3    = (const float*)d_in[14];
    const float* b3    = (const float*)d_in[15];
    float* out = (float*)d_out;

    cudaFuncSetAttribute(fused_mma, cudaFuncAttributeMaxDynamicSharedMemorySize, SM_TOTAL);

    prep_consts<<<1, 512>>>(g1, beta1, m1, v1, b2, g2, beta2, m2, v2, W3);
    prep_W1c<<<(ND * NH1 / 4) / 256, 256>>>(W1);
    prep_F<<<ND / 8, 512>>>(emb, W1);
    dim3 gbp(NB, 4);
    prep_base_partial<<<gbp, 512>>>(rep, W1);
    prep_G_fold<<<NB, 512>>>(b1);
    dim3 gw2(NH1 / 32, NH2 / 32);
    prep_W2t<<<gw2, 256>>>(W2);
    init_out<<<(NB * ND / 4) / 256, 256>>>(out, b3);
    dim3 grid(ND / 128, NH2 / 128, NB);
    fused_mma<<<grid, 256, SM_TOTAL>>>(rep, out);
}

// round 6
// speedup vs baseline: 2.3859x; 1.4859x over previous
#include <cuda_runtime.h>
#include <cuda_bf16.h>
#include <cstdint>

#define NB   64
#define ND   2048
#define NE   64
#define NH1  512
#define NH2  256
#define EPSB 1e-5f

// Scratch (allocation-free)
__device__ float g_W1c[ND * NH1];              // W1d * c1   (4 MB)
__device__ float g_F[ND * NH1];                // emb_h * c1 (4 MB)
__device__ float g_Gp[4 * NB * NH1];
__device__ float g_G[NB * NH1];                // ((rep@W1d)+b1)*c1 + c0
__device__ float g_c1[NH1], g_c0[NH1];
__device__ float g_e1[NH2], g_e0[NH2], g_w3[NH2];
__device__ __nv_bfloat16 g_W2t_hi[NH2 * NH1];  // W2^T hi  [o][h]
__device__ __nv_bfloat16 g_W2t_lo[NH2 * NH1];  // W2^T lo  [o][h]

// ===================== helpers =====================
__device__ __forceinline__ uint32_t smem_u32(const void* p) {
    uint32_t a;
    asm("{ .reg .u64 t; cvta.to.shared.u64 t, %1; cvt.u32.u64 %0, t; }" : "=r"(a) : "l"(p));
    return a;
}
__device__ __forceinline__ void ldsm_x4(uint32_t* r, uint32_t addr) {
    asm volatile("ldmatrix.sync.aligned.m8n8.x4.shared.b16 {%0,%1,%2,%3}, [%4];"
                 : "=r"(r[0]), "=r"(r[1]), "=r"(r[2]), "=r"(r[3]) : "r"(addr));
}
__device__ __forceinline__ void mma_bf16(float* d, const uint32_t* a, const uint32_t* b) {
    asm volatile("mma.sync.aligned.m16n8k16.row.col.f32.bf16.bf16.f32 "
                 "{%0,%1,%2,%3}, {%4,%5,%6,%7}, {%8,%9}, {%0,%1,%2,%3};"
                 : "+f"(d[0]), "+f"(d[1]), "+f"(d[2]), "+f"(d[3])
                 : "r"(a[0]), "r"(a[1]), "r"(a[2]), "r"(a[3]), "r"(b[0]), "r"(b[1]));
}
__device__ __forceinline__ void cpasync16(uint32_t dst, const void* src) {
    asm volatile("cp.async.cg.shared.global [%0], [%1], 16;"
                 :: "r"(dst), "l"(__cvta_generic_to_global(src)) : "memory");
}
#define CP_COMMIT() asm volatile("cp.async.commit_group;" ::: "memory")
#define CP_WAIT0()  asm volatile("cp.async.wait_group 0;" ::: "memory")
#define SWZ(x) ((x) ^ (((x) >> 3) & 0x70))

// ===================== prep kernels =====================
__global__ void prep_consts(const float* __restrict__ g1, const float* __restrict__ beta1,
                            const float* __restrict__ m1, const float* __restrict__ v1,
                            const float* __restrict__ b2, const float* __restrict__ g2,
                            const float* __restrict__ beta2, const float* __restrict__ m2,
                            const float* __restrict__ v2, const float* __restrict__ W3) {
    int t = threadIdx.x;
    if (t < NH1) {
        float c1 = g1[t] * rsqrtf(v1[t] + EPSB);
        g_c1[t] = c1;
        g_c0[t] = beta1[t] - m1[t] * c1;
    }
    if (t < NH2) {
        float e1 = g2[t] * rsqrtf(v2[t] + EPSB);
        g_e1[t] = e1;
        g_e0[t] = (b2[t] - m2[t]) * e1 + beta2[t];
        g_w3[t] = W3[t];
    }
}

__global__ __launch_bounds__(256) void prep_W1c(const float* __restrict__ W1) {
    int i = blockIdx.x * 256 + threadIdx.x;
    float4 w = ((const float4*)W1)[i];
    int h = (i << 2) & (NH1 - 1);
    float4 c = *(const float4*)(g_c1 + h);
    float4 o;
    o.x = w.x * c.x; o.y = w.y * c.y; o.z = w.z * c.z; o.w = w.w * c.w;
    ((float4*)g_W1c)[i] = o;
}

__global__ __launch_bounds__(512) void prep_F(const float* __restrict__ emb,
                                              const float* __restrict__ W1) {
    __shared__ float es[8 * NE];
    int kb = blockIdx.x * 8;
    for (int i = threadIdx.x; i < 8 * NE; i += 512) es[i] = emb[(size_t)kb * NE + i];
    __syncthreads();
    int h = threadIdx.x;
    const float* W1e = W1 + (size_t)ND * NH1;
    float acc[8];
#pragma unroll
    for (int kr = 0; kr < 8; kr++) acc[kr] = 0.f;
#pragma unroll 4
    for (int e = 0; e < NE; e++) {
        float w = W1e[(size_t)e * NH1 + h];
#pragma unroll
        for (int kr = 0; kr < 8; kr++) acc[kr] = fmaf(es[kr * NE + e], w, acc[kr]);
    }
    float c1h = g_c1[h];
#pragma unroll
    for (int kr = 0; kr < 8; kr++) g_F[(size_t)(kb + kr) * NH1 + h] = acc[kr] * c1h;
}

// b-paired split-D partials: grid (NB/2, 4)
__global__ __launch_bounds__(512) void prep_base_partial(const float* __restrict__ rep,
                                                         const float* __restrict__ W1) {
    __shared__ float r2[2][512];
    const int b0 = blockIdx.x * 2;
    const int d0 = blockIdx.y * 512;
    const int h  = threadIdx.x;
    r2[0][h] = rep[(size_t)b0 * ND + d0 + h];
    r2[1][h] = rep[(size_t)(b0 + 1) * ND + d0 + h];
    __syncthreads();
    float a0 = 0.f, a1 = 0.f;
    const float* Wp = W1 + (size_t)d0 * NH1 + h;
#pragma unroll 8
    for (int d = 0; d < 512; d++) {
        float w = Wp[(size_t)d * NH1];
        a0 = fmaf(r2[0][d], w, a0);
        a1 = fmaf(r2[1][d], w, a1);
    }
    g_Gp[((size_t)blockIdx.y * NB + b0) * NH1 + h]     = a0;
    g_Gp[((size_t)blockIdx.y * NB + b0 + 1) * NH1 + h] = a1;
}

__global__ __launch_bounds__(512) void prep_G_fold(const float* __restrict__ b1) {
    const int b = blockIdx.x;
    const int h = threadIdx.x;
    float s = g_Gp[((size_t)0 * NB + b) * NH1 + h]
            + g_Gp[((size_t)1 * NB + b) * NH1 + h]
            + g_Gp[((size_t)2 * NB + b) * NH1 + h]
            + g_Gp[((size_t)3 * NB + b) * NH1 + h];
    g_G[(size_t)b * NH1 + h] = fmaf(s + b1[h], g_c1[h], g_c0[h]);
}

// W2t[o][h] = split-bf16 of W2[h][o]
__global__ __launch_bounds__(256) void prep_W2t(const float* __restrict__ W2) {
    __shared__ float tile[32][33];
    int h0 = blockIdx.x * 32, o0 = blockIdx.y * 32;
    int tx = threadIdx.x & 31, ty = threadIdx.x >> 5;
#pragma unroll
    for (int r = 0; r < 4; r++)
        tile[ty + 8 * r][tx] = W2[(size_t)(h0 + ty + 8 * r) * NH2 + o0 + tx];
    __syncthreads();
#pragma unroll
    for (int r = 0; r < 4; r++) {
        int o = o0 + ty + 8 * r;
        int h = h0 + tx;
        float v = tile[tx][ty + 8 * r];
        __nv_bfloat16 hi = __float2bfloat16_rn(v);
        __nv_bfloat16 lo = __float2bfloat16_rn(v - __bfloat162float(hi));
        g_W2t_hi[(size_t)o * NH1 + h] = hi;
        g_W2t_lo[(size_t)o * NH1 + h] = lo;
    }
}

// ===================== main HMMA kernel =====================
// Grid: (ND/128, NB). 512 threads (16 warps). CTA: 128 rows x 256 cols, K=512 in 8 chunks.
// warp tile 32x64: rowg = wid>>2 (m32), colg = wid&3 (n64). 3-term split-bf16.
// B double-buffered via cp.async.
#define SM_E1      0          // 256 f
#define SM_E0      1024
#define SM_W3      2048
#define SM_G       3072       // 512 f -> 5120
#define SM_REPS    5120       // 128 f -> 5632
#define SM_PART    5632       // 512 f -> 7680
#define SM_AHI     8192       // 16 KB
#define SM_ALO     24576      // 16 KB
#define SM_B       40960      // 2 x (BHI 32KB + BLO 32KB)
#define BUF_STRIDE 65536
#define SM_TOTAL   172032

__global__ __launch_bounds__(512, 1) void fused_mma(
    const float* __restrict__ rep, const float* __restrict__ b3,
    float* __restrict__ out)
{
    extern __shared__ __align__(1024) char smem[];
    const uint32_t sb = smem_u32(smem);
    const int b  = blockIdx.y;
    const int k0 = blockIdx.x * 128;
    const int t  = threadIdx.x;
    const int wid = t >> 5, lane = t & 31;
    const int rowg = wid >> 2, colg = wid & 3;

    // stage constants
    if (t < 256) {
        *(float*)(smem + SM_E1 + t * 4) = g_e1[t];
        *(float*)(smem + SM_E0 + t * 4) = g_e0[t];
        *(float*)(smem + SM_W3 + t * 4) = g_w3[t];
    }
    *(float*)(smem + SM_G + t * 4) = g_G[(size_t)b * NH1 + t];
    if (t < 128) *(float*)(smem + SM_REPS + t * 4) = rep[(size_t)b * ND + k0 + t];
    __syncthreads();

    // ---- B prefetch lambda (hi+lo chunk -> buffer ch&1) ----
    auto loadB = [&](int ch) {
        const int h0 = ch * 64;
        uint32_t bufB = sb + SM_B + (ch & 1) * BUF_STRIDE;
#pragma unroll
        for (int i = 0; i < 4; i++) {
            int idx = t + i * 512;          // 0..2047
            int row = idx >> 3, seg = idx & 7;
            cpasync16(bufB + SWZ(row * 128 + seg * 16),
                      g_W2t_hi + (size_t)row * NH1 + h0 + seg * 8);
        }
#pragma unroll
        for (int i = 0; i < 4; i++) {
            int idx = t + i * 512;
            int row = idx >> 3, seg = idx & 7;
            cpasync16(bufB + 32768 + SWZ(row * 128 + seg * 16),
                      g_W2t_lo + (size_t)row * NH1 + h0 + seg * 8);
        }
        CP_COMMIT();
    };
    loadB(0);

    // ldmatrix address precompute
    uint32_t aBase[2]; int aX[2];
#pragma unroll
    for (int mt = 0; mt < 2; mt++) {
        int rowA = rowg * 32 + mt * 16 + (lane & 15);
        aBase[mt] = sb + SM_AHI + rowA * 128;
        aX[mt]    = (rowA & 7) << 4;
    }
    const int aCol = lane & 16;
    int bRow[4], bX[4];
#pragma unroll
    for (int bt = 0; bt < 4; bt++) {
        int rowB = colg * 64 + bt * 16 + (lane & 7) + ((lane & 16) >> 1);
        bRow[bt] = rowB * 128;
        bX[bt]   = (rowB & 7) << 4;
    }
    const int bCol = (lane & 8) << 1;

    float D[2][8][4];
#pragma unroll
    for (int mt = 0; mt < 2; mt++)
#pragma unroll
        for (int nt = 0; nt < 8; nt++)
#pragma unroll
            for (int j = 0; j < 4; j++) D[mt][nt][j] = 0.f;

    const int krow = t >> 2;          // 0..127
    const int hb   = (t & 3) * 16;    // h base within 64-chunk
    const float rp = *(const float*)(smem + SM_REPS + krow * 4);

#pragma unroll 1
    for (int ch = 0; ch < 8; ch++) {
        const int h0 = ch * 64;
        // ---- build A_hi / A_lo (128 x 64 bf16, SW128), 16 h per thread ----
#pragma unroll
        for (int half = 0; half < 2; half++) {
            uint32_t hv[4], lv[4];
#pragma unroll
            for (int j = 0; j < 2; j++) {
                int h4 = hb + half * 8 + j * 4;
                size_t goff = (size_t)(k0 + krow) * NH1 + h0 + h4;
                float4 wv = *(const float4*)(g_W1c + goff);
                float4 fv = *(const float4*)(g_F + goff);
                float4 gv = *(const float4*)(smem + SM_G + (h0 + h4) * 4);
                float u0 = fmaxf(gv.x + fv.x - rp * wv.x, 0.f);
                float u1 = fmaxf(gv.y + fv.y - rp * wv.y, 0.f);
                float u2 = fmaxf(gv.z + fv.z - rp * wv.z, 0.f);
                float u3 = fmaxf(gv.w + fv.w - rp * wv.w, 0.f);
                __nv_bfloat16 h0b = __float2bfloat16_rn(u0);
                __nv_bfloat16 h1b = __float2bfloat16_rn(u1);
                __nv_bfloat16 h2b = __float2bfloat16_rn(u2);
                __nv_bfloat16 h3b = __float2bfloat16_rn(u3);
                __nv_bfloat16 l0b = __float2bfloat16_rn(u0 - __bfloat162float(h0b));
                __nv_bfloat16 l1b = __float2bfloat16_rn(u1 - __bfloat162float(h1b));
                __nv_bfloat16 l2b = __float2bfloat16_rn(u2 - __bfloat162float(h2b));
                __nv_bfloat16 l3b = __float2bfloat16_rn(u3 - __bfloat162float(h3b));
                hv[2 * j]     = ((uint32_t)__bfloat16_as_ushort(h1b) << 16) | __bfloat16_as_ushort(h0b);
                hv[2 * j + 1] = ((uint32_t)__bfloat16_as_ushort(h3b) << 16) | __bfloat16_as_ushort(h2b);
                lv[2 * j]     = ((uint32_t)__bfloat16_as_ushort(l1b) << 16) | __bfloat16_as_ushort(l0b);
                lv[2 * j + 1] = ((uint32_t)__bfloat16_as_ushort(l3b) << 16) | __bfloat16_as_ushort(l2b);
            }
            uint32_t boff = SWZ(krow * 128 + (hb + half * 8) * 2);
            *(uint4*)(smem + SM_AHI + boff) = make_uint4(hv[0], hv[1], hv[2], hv[3]);
            *(uint4*)(smem + SM_ALO + boff) = make_uint4(lv[0], lv[1], lv[2], lv[3]);
        }
        CP_WAIT0();
        __syncthreads();
        if (ch < 7) loadB(ch + 1);

        const uint32_t bufB = sb + SM_B + (ch & 1) * BUF_STRIDE;
        // ---- 4 k-steps of 16; 3 MMA terms ----
#pragma unroll
        for (int ks = 0; ks < 4; ks++) {
            const int cA = ks * 32 + aCol;
            const int cB = ks * 32 + bCol;
            uint32_t ah[2][4], al[2][4];
            ldsm_x4(ah[0], aBase[0] + (cA ^ aX[0]));
            ldsm_x4(ah[1], aBase[1] + (cA ^ aX[1]));
            ldsm_x4(al[0], aBase[0] + 16384 + (cA ^ aX[0]));
            ldsm_x4(al[1], aBase[1] + 16384 + (cA ^ aX[1]));
#pragma unroll
            for (int bth = 0; bth < 2; bth++) {
                uint32_t bh[2][4], bl[2][4];
#pragma unroll
                for (int bb = 0; bb < 2; bb++) {
                    int bt = 2 * bth + bb;
                    ldsm_x4(bh[bb], bufB + bRow[bt] + (cB ^ bX[bt]));
                }
#pragma unroll
                for (int mt = 0; mt < 2; mt++)
#pragma unroll
                    for (int bb = 0; bb < 2; bb++) {
                        int nt = 4 * bth + 2 * bb;
                        mma_bf16(D[mt][nt],     ah[mt], bh[bb]);
                        mma_bf16(D[mt][nt + 1], ah[mt], bh[bb] + 2);
                        mma_bf16(D[mt][nt],     al[mt], bh[bb]);
                        mma_bf16(D[mt][nt + 1], al[mt], bh[bb] + 2);
                    }
#pragma unroll
                for (int bb = 0; bb < 2; bb++) {
                    int bt = 2 * bth + bb;
                    ldsm_x4(bl[bb], bufB + 32768 + bRow[bt] + (cB ^ bX[bt]));
                }
#pragma unroll
                for (int mt = 0; mt < 2; mt++)
#pragma unroll
                    for (int bb = 0; bb < 2; bb++) {
                        int nt = 4 * bth + 2 * bb;
                        mma_bf16(D[mt][nt],     ah[mt], bl[bb]);
                        mma_bf16(D[mt][nt + 1], ah[mt], bl[bb] + 2);
                    }
            }
        }
        __syncthreads();
    }

    // ---- epilogue: BN2 + relu + W3 dot, reduce over o ----
#pragma unroll
    for (int mt = 0; mt < 2; mt++) {
        int r = rowg * 32 + mt * 16 + (lane >> 2);
        float s0 = 0.f, s1 = 0.f;
#pragma unroll
        for (int nt = 0; nt < 8; nt++) {
#pragma unroll
            for (int j = 0; j < 2; j++) {
                int o = colg * 64 + nt * 8 + 2 * (lane & 3) + j;
                float e1 = *(const float*)(smem + SM_E1 + o * 4);
                float e0 = *(const float*)(smem + SM_E0 + o * 4);
                float w3 = *(const float*)(smem + SM_W3 + o * 4);
                s0 = fmaf(fmaxf(fmaf(D[mt][nt][j],     e1, e0), 0.f), w3, s0);
                s1 = fmaf(fmaxf(fmaf(D[mt][nt][2 + j], e1, e0), 0.f), w3, s1);
            }
        }
        s0 += __shfl_xor_sync(0xffffffffu, s0, 1);
        s0 += __shfl_xor_sync(0xffffffffu, s0, 2);
        s1 += __shfl_xor_sync(0xffffffffu, s1, 1);
        s1 += __shfl_xor_sync(0xffffffffu, s1, 2);
        if ((lane & 3) == 0) {
            *(float*)(smem + SM_PART + (colg * 128 + r) * 4)     = s0;
            *(float*)(smem + SM_PART + (colg * 128 + r + 8) * 4) = s1;
        }
    }
    __syncthreads();
    if (t < 128) {
        float v = *(const float*)(smem + SM_PART + t * 4)
                + *(const float*)(smem + SM_PART + (128 + t) * 4)
                + *(const float*)(smem + SM_PART + (256 + t) * 4)
                + *(const float*)(smem + SM_PART + (384 + t) * 4);
        out[(size_t)b * ND + k0 + t] = v + b3[0];
    }
}

extern "C" void kernel_launch(void* const* d_in, const int* in_sizes, int n_in,
                              void* d_out, int out_size) {
    const float* rep   = (const float*)d_in[0];
    const float* emb   = (const float*)d_in[1];
    const float* W1    = (const float*)d_in[2];
    const float* b1    = (const float*)d_in[3];
    const float* g1    = (const float*)d_in[4];
    const float* beta1 = (const float*)d_in[5];
    const float* m1    = (const float*)d_in[6];
    const float* v1    = (const float*)d_in[7];
    const float* W2    = (const float*)d_in[8];
    const float* b2    = (const float*)d_in[9];
    const float* g2    = (const float*)d_in[10];
    const float* beta2 = (const float*)d_in[11];
    const float* m2    = (const float*)d_in[12];
    const float* v2    = (const float*)d_in[13];
    const float* W3    = (const float*)d_in[14];
    const float* b3    = (const float*)d_in[15];
    float* out = (float*)d_out;

    cudaFuncSetAttribute(fused_mma, cudaFuncAttributeMaxDynamicSharedMemorySize, SM_TOTAL);

    prep_consts<<<1, 512>>>(g1, beta1, m1, v1, b2, g2, beta2, m2, v2, W3);
    prep_W1c<<<(ND * NH1 / 4) / 256, 256>>>(W1);
    prep_F<<<ND / 8, 512>>>(emb, W1);
    dim3 gbp(NB / 2, 4);
    prep_base_partial<<<gbp, 512>>>(rep, W1);
    prep_G_fold<<<NB, 512>>>(b1);
    dim3 gw2(NH1 / 32, NH2 / 32);
    prep_W2t<<<gw2, 256>>>(W2);
    dim3 grid(ND / 128, NB);
    fused_mma<<<grid, 512, SM_TOTAL>>>(rep, b3, out);
}

// round 7
// speedup vs baseline: 2.5676x; 1.0762x over previous
#include <cuda_runtime.h>
#include <cuda_bf16.h>
#include <cstdint>

#define NB   64
#define ND   2048
#define NE   64
#define NH1  512
#define NH2  256
#define EPSB 1e-5f

// Scratch (allocation-free)
__device__ float g_W1c[ND * NH1];              // W1d * c1   (4 MB)
__device__ float g_F[ND * NH1];                // emb_h * c1 (4 MB)
__device__ float g_Gp[4 * NB * NH1];
__device__ float g_G[NB * NH1];                // ((rep@W1d)+b1)*c1 + c0
__device__ float g_c1[NH1], g_c0[NH1];
__device__ float g_e1[NH2], g_e0[NH2], g_w3[NH2];
__device__ __nv_bfloat16 g_W2t_hi[NH2 * NH1];  // W2^T hi  [o][h]
__device__ __nv_bfloat16 g_W2t_lo[NH2 * NH1];  // W2^T lo  [o][h]

// ===================== helpers =====================
__device__ __forceinline__ uint32_t smem_u32(const void* p) {
    uint32_t a;
    asm("{ .reg .u64 t; cvta.to.shared.u64 t, %1; cvt.u32.u64 %0, t; }" : "=r"(a) : "l"(p));
    return a;
}
__device__ __forceinline__ void ldsm_x4(uint32_t* r, uint32_t addr) {
    asm volatile("ldmatrix.sync.aligned.m8n8.x4.shared.b16 {%0,%1,%2,%3}, [%4];"
                 : "=r"(r[0]), "=r"(r[1]), "=r"(r[2]), "=r"(r[3]) : "r"(addr));
}
__device__ __forceinline__ void mma_bf16(float* d, const uint32_t* a, const uint32_t* b) {
    asm volatile("mma.sync.aligned.m16n8k16.row.col.f32.bf16.bf16.f32 "
                 "{%0,%1,%2,%3}, {%4,%5,%6,%7}, {%8,%9}, {%0,%1,%2,%3};"
                 : "+f"(d[0]), "+f"(d[1]), "+f"(d[2]), "+f"(d[3])
                 : "r"(a[0]), "r"(a[1]), "r"(a[2]), "r"(a[3]), "r"(b[0]), "r"(b[1]));
}
__device__ __forceinline__ void cpasync16(uint32_t dst, const void* src) {
    asm volatile("cp.async.cg.shared.global [%0], [%1], 16;"
                 :: "r"(dst), "l"(__cvta_generic_to_global(src)) : "memory");
}
#define CP_COMMIT() asm volatile("cp.async.commit_group;" ::: "memory")
#define CP_WAIT0()  asm volatile("cp.async.wait_group 0;" ::: "memory")
#define SWZ(x) ((x) ^ (((x) >> 3) & 0x70))

// ===================== prep kernels (3 launches total before main) =====================
__global__ void prep_consts(const float* __restrict__ g1, const float* __restrict__ beta1,
                            const float* __restrict__ m1, const float* __restrict__ v1,
                            const float* __restrict__ b2, const float* __restrict__ g2,
                            const float* __restrict__ beta2, const float* __restrict__ m2,
                            const float* __restrict__ v2, const float* __restrict__ W3) {
    int t = threadIdx.x;
    if (t < NH1) {
        float c1 = g1[t] * rsqrtf(v1[t] + EPSB);
        g_c1[t] = c1;
        g_c0[t] = beta1[t] - m1[t] * c1;
    }
    if (t < NH2) {
        float e1 = g2[t] * rsqrtf(v2[t] + EPSB);
        g_e1[t] = e1;
        g_e0[t] = (b2[t] - m2[t]) * e1 + beta2[t];
        g_w3[t] = W3[t];
    }
}

// Mega-prep: blockIdx ranges
//  [0, 512)    : W1c scale         (512 threads, 1 float4 each)
//  [512, 768)  : F = (emb@W1e)*c1  (8 k-rows per CTA)
//  [768, 896)  : base partials     (b-paired, 4 d-slices)
//  [896, 1024) : W2t split-bf16 transpose
__global__ __launch_bounds__(512) void mega_prep(const float* __restrict__ rep,
                                                 const float* __restrict__ emb,
                                                 const float* __restrict__ W1,
                                                 const float* __restrict__ W2) {
    __shared__ float sh[2 * 512];
    const int cb = blockIdx.x;
    const int t  = threadIdx.x;
    if (cb < 512) {
        int i = cb * 512 + t;       // float4 index, 262144 total
        float4 w = ((const float4*)W1)[i];
        int h = (i << 2) & (NH1 - 1);
        float4 c = *(const float4*)(g_c1 + h);
        float4 o;
        o.x = w.x * c.x; o.y = w.y * c.y; o.z = w.z * c.z; o.w = w.w * c.w;
        ((float4*)g_W1c)[i] = o;
    } else if (cb < 768) {
        int kb = (cb - 512) * 8;
        for (int i = t; i < 8 * NE; i += 512) sh[i] = emb[(size_t)kb * NE + i];
        __syncthreads();
        const float* W1e = W1 + (size_t)ND * NH1;
        float acc[8];
#pragma unroll
        for (int kr = 0; kr < 8; kr++) acc[kr] = 0.f;
#pragma unroll 4
        for (int e = 0; e < NE; e++) {
            float w = W1e[(size_t)e * NH1 + t];
#pragma unroll
            for (int kr = 0; kr < 8; kr++) acc[kr] = fmaf(sh[kr * NE + e], w, acc[kr]);
        }
        float c1h = g_c1[t];
#pragma unroll
        for (int kr = 0; kr < 8; kr++) g_F[(size_t)(kb + kr) * NH1 + t] = acc[kr] * c1h;
    } else if (cb < 896) {
        int idx = cb - 768;                 // 0..127
        int b0  = (idx & 31) * 2;           // paired b
        int d0  = (idx >> 5) * 512;         // 4 slices
        sh[t]       = rep[(size_t)b0 * ND + d0 + t];
        sh[512 + t] = rep[(size_t)(b0 + 1) * ND + d0 + t];
        __syncthreads();
        float a0 = 0.f, a1 = 0.f;
        const float* Wp = W1 + (size_t)d0 * NH1 + t;
#pragma unroll 8
        for (int d = 0; d < 512; d++) {
            float w = Wp[(size_t)d * NH1];
            a0 = fmaf(sh[d], w, a0);
            a1 = fmaf(sh[512 + d], w, a1);
        }
        g_Gp[((size_t)(idx >> 5) * NB + b0) * NH1 + t]     = a0;
        g_Gp[((size_t)(idx >> 5) * NB + b0 + 1) * NH1 + t] = a1;
    } else {
        int idx = cb - 896;                 // 0..127
        int h0 = (idx & 15) * 32, o0 = (idx >> 4) * 32;
        float (*tile)[33] = (float (*)[33])sh;    // 32x33 fits in 2*512? 1056 floats > 1024!
        // use a dedicated path: 512 threads, each handles 2 elements of the 32x32 tile
        int tx = t & 31, ty = t >> 5;       // ty 0..15
#pragma unroll
        for (int r = 0; r < 2; r++) {
            int row = ty + 16 * r;
            // direct transpose read (uncoalesced on one side but tile is tiny)
            float v = W2[(size_t)(h0 + tx) * NH2 + o0 + row];
            __nv_bfloat16 hi = __float2bfloat16_rn(v);
            __nv_bfloat16 lo = __float2bfloat16_rn(v - __bfloat162float(hi));
            g_W2t_hi[(size_t)(o0 + row) * NH1 + h0 + tx] = hi;
            g_W2t_lo[(size_t)(o0 + row) * NH1 + h0 + tx] = lo;
        }
        (void)tile;
    }
}

__global__ __launch_bounds__(512) void prep_G_fold(const float* __restrict__ b1) {
    const int b = blockIdx.x;
    const int h = threadIdx.x;
    float s = g_Gp[((size_t)0 * NB + b) * NH1 + h]
            + g_Gp[((size_t)1 * NB + b) * NH1 + h]
            + g_Gp[((size_t)2 * NB + b) * NH1 + h]
            + g_Gp[((size_t)3 * NB + b) * NH1 + h];
    g_G[(size_t)b * NH1 + h] = fmaf(s + b1[h], g_c1[h], g_c0[h]);
}

// ===================== main HMMA kernel =====================
// Grid: (ND/128, NB). 512 threads (16 warps). CTA: 128 rows x 256 cols, K=512 in 8 chunks.
// A and B both double-buffered; loop body: MMA(ch) then build A(ch+1) (overlap).
#define SM_E1      0          // 256 f
#define SM_E0      1024
#define SM_W3      2048
#define SM_G       3072       // 512 f -> 5120
#define SM_REPS    5120       // 128 f -> 5632
#define SM_PART    5632       // 512 f -> 7680
#define SM_A       8192       // 2 x (AHI 16KB + ALO 16KB) = 64 KB
#define A_STRIDE   32768
#define SM_B       73728      // 2 x (BHI 32KB + BLO 32KB) = 128 KB
#define BUF_STRIDE 65536
#define SM_TOTAL   204800

__global__ __launch_bounds__(512, 1) void fused_mma(
    const float* __restrict__ rep, const float* __restrict__ b3,
    float* __restrict__ out)
{
    extern __shared__ __align__(1024) char smem[];
    const uint32_t sb = smem_u32(smem);
    const int b  = blockIdx.y;
    const int k0 = blockIdx.x * 128;
    const int t  = threadIdx.x;
    const int wid = t >> 5, lane = t & 31;
    const int rowg = wid >> 2, colg = wid & 3;

    // stage constants
    if (t < 256) {
        *(float*)(smem + SM_E1 + t * 4) = g_e1[t];
        *(float*)(smem + SM_E0 + t * 4) = g_e0[t];
        *(float*)(smem + SM_W3 + t * 4) = g_w3[t];
    }
    *(float*)(smem + SM_G + t * 4) = g_G[(size_t)b * NH1 + t];
    if (t < 128) *(float*)(smem + SM_REPS + t * 4) = rep[(size_t)b * ND + k0 + t];
    __syncthreads();

    auto loadB = [&](int ch) {
        const int h0 = ch * 64;
        uint32_t bufB = sb + SM_B + (ch & 1) * BUF_STRIDE;
#pragma unroll
        for (int i = 0; i < 4; i++) {
            int idx = t + i * 512;
            int row = idx >> 3, seg = idx & 7;
            cpasync16(bufB + SWZ(row * 128 + seg * 16),
                      g_W2t_hi + (size_t)row * NH1 + h0 + seg * 8);
        }
#pragma unroll
        for (int i = 0; i < 4; i++) {
            int idx = t + i * 512;
            int row = idx >> 3, seg = idx & 7;
            cpasync16(bufB + 32768 + SWZ(row * 128 + seg * 16),
                      g_W2t_lo + (size_t)row * NH1 + h0 + seg * 8);
        }
        CP_COMMIT();
    };

    const int krow = t >> 2;          // 0..127
    const int hb   = (t & 3) * 16;    // h base within 64-chunk
    const float rp = *(const float*)(smem + SM_REPS + krow * 4);

    auto buildA = [&](int ch) {
        const int h0 = ch * 64;
        uint32_t bufA = sb + SM_A + (ch & 1) * A_STRIDE;
#pragma unroll
        for (int half = 0; half < 2; half++) {
            uint32_t hv[4], lv[4];
#pragma unroll
            for (int j = 0; j < 2; j++) {
                int h4 = hb + half * 8 + j * 4;
                size_t goff = (size_t)(k0 + krow) * NH1 + h0 + h4;
                float4 wv = *(const float4*)(g_W1c + goff);
                float4 fv = *(const float4*)(g_F + goff);
                float4 gv = *(const float4*)(smem + SM_G + (h0 + h4) * 4);
                float u0 = fmaxf(gv.x + fv.x - rp * wv.x, 0.f);
                float u1 = fmaxf(gv.y + fv.y - rp * wv.y, 0.f);
                float u2 = fmaxf(gv.z + fv.z - rp * wv.z, 0.f);
                float u3 = fmaxf(gv.w + fv.w - rp * wv.w, 0.f);
                __nv_bfloat16 h0b = __float2bfloat16_rn(u0);
                __nv_bfloat16 h1b = __float2bfloat16_rn(u1);
                __nv_bfloat16 h2b = __float2bfloat16_rn(u2);
                __nv_bfloat16 h3b = __float2bfloat16_rn(u3);
                __nv_bfloat16 l0b = __float2bfloat16_rn(u0 - __bfloat162float(h0b));
                __nv_bfloat16 l1b = __float2bfloat16_rn(u1 - __bfloat162float(h1b));
                __nv_bfloat16 l2b = __float2bfloat16_rn(u2 - __bfloat162float(h2b));
                __nv_bfloat16 l3b = __float2bfloat16_rn(u3 - __bfloat162float(h3b));
                hv[2 * j]     = ((uint32_t)__bfloat16_as_ushort(h1b) << 16) | __bfloat16_as_ushort(h0b);
                hv[2 * j + 1] = ((uint32_t)__bfloat16_as_ushort(h3b) << 16) | __bfloat16_as_ushort(h2b);
                lv[2 * j]     = ((uint32_t)__bfloat16_as_ushort(l1b) << 16) | __bfloat16_as_ushort(l0b);
                lv[2 * j + 1] = ((uint32_t)__bfloat16_as_ushort(l3b) << 16) | __bfloat16_as_ushort(l2b);
            }
            uint32_t boff = SWZ(krow * 128 + (hb + half * 8) * 2);
            *(uint4*)(smem + SM_A + (ch & 1) * A_STRIDE + boff) = make_uint4(hv[0], hv[1], hv[2], hv[3]);
            *(uint4*)(smem + SM_A + (ch & 1) * A_STRIDE + 16384 + boff) = make_uint4(lv[0], lv[1], lv[2], lv[3]);
        }
        (void)bufA;
    };

    // ldmatrix address precompute (offsets relative to A/B buffer base)
    uint32_t aOff[2]; int aX[2];
#pragma unroll
    for (int mt = 0; mt < 2; mt++) {
        int rowA = rowg * 32 + mt * 16 + (lane & 15);
        aOff[mt] = rowA * 128;
        aX[mt]   = (rowA & 7) << 4;
    }
    const int aCol = lane & 16;
    int bRow[4], bX[4];
#pragma unroll
    for (int bt = 0; bt < 4; bt++) {
        int rowB = colg * 64 + bt * 16 + (lane & 7) + ((lane & 16) >> 1);
        bRow[bt] = rowB * 128;
        bX[bt]   = (rowB & 7) << 4;
    }
    const int bCol = (lane & 8) << 1;

    float D[2][8][4];
#pragma unroll
    for (int mt = 0; mt < 2; mt++)
#pragma unroll
        for (int nt = 0; nt < 8; nt++)
#pragma unroll
            for (int j = 0; j < 4; j++) D[mt][nt][j] = 0.f;

    // prologue: B(0) + A(0)
    loadB(0);
    buildA(0);
    CP_WAIT0();
    __syncthreads();

#pragma unroll 1
    for (int ch = 0; ch < 8; ch++) {
        if (ch < 7) loadB(ch + 1);
        const uint32_t bufA = sb + SM_A + (ch & 1) * A_STRIDE;
        const uint32_t bufB = sb + SM_B + (ch & 1) * BUF_STRIDE;
        // ---- MMA(ch): 4 k-steps of 16; 3 terms ----
#pragma unroll
        for (int ks = 0; ks < 4; ks++) {
            const int cA = ks * 32 + aCol;
            const int cB = ks * 32 + bCol;
            uint32_t ah[2][4], al[2][4];
            ldsm_x4(ah[0], bufA + aOff[0] + (cA ^ aX[0]));
            ldsm_x4(ah[1], bufA + aOff[1] + (cA ^ aX[1]));
            ldsm_x4(al[0], bufA + 16384 + aOff[0] + (cA ^ aX[0]));
            ldsm_x4(al[1], bufA + 16384 + aOff[1] + (cA ^ aX[1]));
#pragma unroll
            for (int bth = 0; bth < 2; bth++) {
                uint32_t bh[2][4], bl[2][4];
#pragma unroll
                for (int bb = 0; bb < 2; bb++) {
                    int bt = 2 * bth + bb;
                    ldsm_x4(bh[bb], bufB + bRow[bt] + (cB ^ bX[bt]));
                }
#pragma unroll
                for (int mt = 0; mt < 2; mt++)
#pragma unroll
                    for (int bb = 0; bb < 2; bb++) {
                        int nt = 4 * bth + 2 * bb;
                        mma_bf16(D[mt][nt],     ah[mt], bh[bb]);
                        mma_bf16(D[mt][nt + 1], ah[mt], bh[bb] + 2);
                        mma_bf16(D[mt][nt],     al[mt], bh[bb]);
                        mma_bf16(D[mt][nt + 1], al[mt], bh[bb] + 2);
                    }
#pragma unroll
                for (int bb = 0; bb < 2; bb++) {
                    int bt = 2 * bth + bb;
                    ldsm_x4(bl[bb], bufB + 32768 + bRow[bt] + (cB ^ bX[bt]));
                }
#pragma unroll
                for (int mt = 0; mt < 2; mt++)
#pragma unroll
                    for (int bb = 0; bb < 2; bb++) {
                        int nt = 4 * bth + 2 * bb;
                        mma_bf16(D[mt][nt],     ah[mt], bl[bb]);
                        mma_bf16(D[mt][nt + 1], ah[mt], bl[bb] + 2);
                    }
            }
        }
        // ---- build A(ch+1) overlapped behind other warps' MMA ----
        if (ch < 7) buildA(ch + 1);
        CP_WAIT0();
        __syncthreads();
    }

    // ---- epilogue: BN2 + relu + W3 dot, reduce over o ----
#pragma unroll
    for (int mt = 0; mt < 2; mt++) {
        int r = rowg * 32 + mt * 16 + (lane >> 2);
        float s0 = 0.f, s1 = 0.f;
#pragma unroll
        for (int nt = 0; nt < 8; nt++) {
#pragma unroll
            for (int j = 0; j < 2; j++) {
                int o = colg * 64 + nt * 8 + 2 * (lane & 3) + j;
                float e1 = *(const float*)(smem + SM_E1 + o * 4);
                float e0 = *(const float*)(smem + SM_E0 + o * 4);
                float w3 = *(const float*)(smem + SM_W3 + o * 4);
                s0 = fmaf(fmaxf(fmaf(D[mt][nt][j],     e1, e0), 0.f), w3, s0);
                s1 = fmaf(fmaxf(fmaf(D[mt][nt][2 + j], e1, e0), 0.f), w3, s1);
            }
        }
        s0 += __shfl_xor_sync(0xffffffffu, s0, 1);
        s0 += __shfl_xor_sync(0xffffffffu, s0, 2);
        s1 += __shfl_xor_sync(0xffffffffu, s1, 1);
        s1 += __shfl_xor_sync(0xffffffffu, s1, 2);
        if ((lane & 3) == 0) {
            *(float*)(smem + SM_PART + (colg * 128 + r) * 4)     = s0;
            *(float*)(smem + SM_PART + (colg * 128 + r + 8) * 4) = s1;
        }
    }
    __syncthreads();
    if (t < 128) {
        float v = *(const float*)(smem + SM_PART + t * 4)
                + *(const float*)(smem + SM_PART + (128 + t) * 4)
                + *(const float*)(smem + SM_PART + (256 + t) * 4)
                + *(const float*)(smem + SM_PART + (384 + t) * 4);
        out[(size_t)b * ND + k0 + t] = v + b3[0];
    }
}

extern "C" void kernel_launch(void* const* d_in, const int* in_sizes, int n_in,
                              void* d_out, int out_size) {
    const float* rep   = (const float*)d_in[0];
    const float* emb   = (const float*)d_in[1];
    const float* W1    = (const float*)d_in[2];
    const float* b1    = (const float*)d_in[3];
    const float* g1    = (const float*)d_in[4];
    const float* beta1 = (const float*)d_in[5];
    const float* m1    = (const float*)d_in[6];
    const float* v1    = (const float*)d_in[7];
    const float* W2    = (const float*)d_in[8];
    const float* b2    = (const float*)d_in[9];
    const float* g2    = (const float*)d_in[10];
    const float* beta2 = (const float*)d_in[11];
    const float* m2    = (const float*)d_in[12];
    const float* v2    = (const float*)d_in[13];
    const float* W3    = (const float*)d_in[14];
    const float* b3    = (const float*)d_in[15];
    float* out = (float*)d_out;

    cudaFuncSetAttribute(fused_mma, cudaFuncAttributeMaxDynamicSharedMemorySize, SM_TOTAL);

    prep_consts<<<1, 512>>>(g1, beta1, m1, v1, b2, g2, beta2, m2, v2, W3);   // 0
    mega_prep<<<1024, 512>>>(rep, emb, W1, W2);                              // 1
    prep_G_fold<<<NB, 512>>>(b1);                                            // 2
    dim3 grid(ND / 128, NB);
    fused_mma<<<grid, 512, SM_TOTAL>>>(rep, b3, out);                        // 3 (profiled)
}

// round 8
// speedup vs baseline: 2.7245x; 1.0611x over previous
#include <cuda_runtime.h>
#include <cuda_bf16.h>
#include <cstdint>

#define NB   64
#define ND   2048
#define NE   64
#define NH1  512
#define NH2  256
#define EPSB 1e-5f

// Scratch (allocation-free)
__device__ float g_W1c[ND * NH1];              // W1d * c1   (4 MB)
__device__ float g_F[ND * NH1];                // emb_h * c1 (4 MB)
__device__ float g_Gp[4 * NB * NH1];
__device__ float g_G[NB * NH1];                // ((rep@W1d)+b1)*c1 + c0
__device__ float g_c1[NH1], g_c0[NH1];
__device__ float g_e1[NH2], g_e0[NH2], g_w3[NH2];
__device__ __nv_bfloat16 g_W2t_hi[NH2 * NH1];  // W2^T hi  [o][h]
__device__ __nv_bfloat16 g_W2t_lo[NH2 * NH1];  // W2^T lo  [o][h]

// ===================== helpers =====================
__device__ __forceinline__ uint32_t smem_u32(const void* p) {
    uint32_t a;
    asm("{ .reg .u64 t; cvta.to.shared.u64 t, %1; cvt.u32.u64 %0, t; }" : "=r"(a) : "l"(p));
    return a;
}
__device__ __forceinline__ void ldsm_x4(uint32_t* r, uint32_t addr) {
    asm volatile("ldmatrix.sync.aligned.m8n8.x4.shared.b16 {%0,%1,%2,%3}, [%4];"
                 : "=r"(r[0]), "=r"(r[1]), "=r"(r[2]), "=r"(r[3]) : "r"(addr));
}
__device__ __forceinline__ void mma_bf16(float* d, const uint32_t* a, const uint32_t* b) {
    asm volatile("mma.sync.aligned.m16n8k16.row.col.f32.bf16.bf16.f32 "
                 "{%0,%1,%2,%3}, {%4,%5,%6,%7}, {%8,%9}, {%0,%1,%2,%3};"
                 : "+f"(d[0]), "+f"(d[1]), "+f"(d[2]), "+f"(d[3])
                 : "r"(a[0]), "r"(a[1]), "r"(a[2]), "r"(a[3]), "r"(b[0]), "r"(b[1]));
}
__device__ __forceinline__ void cpasync16(uint32_t dst, const void* src) {
    asm volatile("cp.async.cg.shared.global [%0], [%1], 16;"
                 :: "r"(dst), "l"(__cvta_generic_to_global(src)) : "memory");
}
#define CP_COMMIT() asm volatile("cp.async.commit_group;" ::: "memory")
#define CP_WAIT0()  asm volatile("cp.async.wait_group 0;" ::: "memory")
#define SWZ(x) ((x) ^ (((x) >> 3) & 0x70))

// ===================== prep kernels (3 launches before main) =====================
__global__ void prep_consts(const float* __restrict__ g1, const float* __restrict__ beta1,
                            const float* __restrict__ m1, const float* __restrict__ v1,
                            const float* __restrict__ b2, const float* __restrict__ g2,
                            const float* __restrict__ beta2, const float* __restrict__ m2,
                            const float* __restrict__ v2, const float* __restrict__ W3) {
    int t = threadIdx.x;
    if (t < NH1) {
        float c1 = g1[t] * rsqrtf(v1[t] + EPSB);
        g_c1[t] = c1;
        g_c0[t] = beta1[t] - m1[t] * c1;
    }
    if (t < NH2) {
        float e1 = g2[t] * rsqrtf(v2[t] + EPSB);
        g_e1[t] = e1;
        g_e0[t] = (b2[t] - m2[t]) * e1 + beta2[t];
        g_w3[t] = W3[t];
    }
}

__global__ __launch_bounds__(512) void mega_prep(const float* __restrict__ rep,
                                                 const float* __restrict__ emb,
                                                 const float* __restrict__ W1,
                                                 const float* __restrict__ W2) {
    __shared__ float sh[2 * 512];
    const int cb = blockIdx.x;
    const int t  = threadIdx.x;
    if (cb < 512) {
        int i = cb * 512 + t;
        float4 w = ((const float4*)W1)[i];
        int h = (i << 2) & (NH1 - 1);
        float4 c = *(const float4*)(g_c1 + h);
        float4 o;
        o.x = w.x * c.x; o.y = w.y * c.y; o.z = w.z * c.z; o.w = w.w * c.w;
        ((float4*)g_W1c)[i] = o;
    } else if (cb < 768) {
        int kb = (cb - 512) * 8;
        for (int i = t; i < 8 * NE; i += 512) sh[i] = emb[(size_t)kb * NE + i];
        __syncthreads();
        const float* W1e = W1 + (size_t)ND * NH1;
        float acc[8];
#pragma unroll
        for (int kr = 0; kr < 8; kr++) acc[kr] = 0.f;
#pragma unroll 4
        for (int e = 0; e < NE; e++) {
            float w = W1e[(size_t)e * NH1 + t];
#pragma unroll
            for (int kr = 0; kr < 8; kr++) acc[kr] = fmaf(sh[kr * NE + e], w, acc[kr]);
        }
        float c1h = g_c1[t];
#pragma unroll
        for (int kr = 0; kr < 8; kr++) g_F[(size_t)(kb + kr) * NH1 + t] = acc[kr] * c1h;
    } else if (cb < 896) {
        int idx = cb - 768;
        int b0  = (idx & 31) * 2;
        int d0  = (idx >> 5) * 512;
        sh[t]       = rep[(size_t)b0 * ND + d0 + t];
        sh[512 + t] = rep[(size_t)(b0 + 1) * ND + d0 + t];
        __syncthreads();
        float a0 = 0.f, a1 = 0.f;
        const float* Wp = W1 + (size_t)d0 * NH1 + t;
#pragma unroll 8
        for (int d = 0; d < 512; d++) {
            float w = Wp[(size_t)d * NH1];
            a0 = fmaf(sh[d], w, a0);
            a1 = fmaf(sh[512 + d], w, a1);
        }
        g_Gp[((size_t)(idx >> 5) * NB + b0) * NH1 + t]     = a0;
        g_Gp[((size_t)(idx >> 5) * NB + b0 + 1) * NH1 + t] = a1;
    } else {
        int idx = cb - 896;
        int h0 = (idx & 15) * 32, o0 = (idx >> 4) * 32;
        int tx = t & 31, ty = t >> 5;
#pragma unroll
        for (int r = 0; r < 2; r++) {
            int row = ty + 16 * r;
            float v = W2[(size_t)(h0 + tx) * NH2 + o0 + row];
            __nv_bfloat16 hi = __float2bfloat16_rn(v);
            __nv_bfloat16 lo = __float2bfloat16_rn(v - __bfloat162float(hi));
            g_W2t_hi[(size_t)(o0 + row) * NH1 + h0 + tx] = hi;
            g_W2t_lo[(size_t)(o0 + row) * NH1 + h0 + tx] = lo;
        }
    }
}

__global__ __launch_bounds__(512) void prep_G_fold(const float* __restrict__ b1) {
    const int b = blockIdx.x;
    const int h = threadIdx.x;
    float s = g_Gp[((size_t)0 * NB + b) * NH1 + h]
            + g_Gp[((size_t)1 * NB + b) * NH1 + h]
            + g_Gp[((size_t)2 * NB + b) * NH1 + h]
            + g_Gp[((size_t)3 * NB + b) * NH1 + h];
    g_G[(size_t)b * NH1 + h] = fmaf(s + b1[h], g_c1[h], g_c0[h]);
}

// ===================== main HMMA kernel =====================
// Grid: (ND/64, NB). 256 threads (8 warps). CTA: 64 rows x 256 cols, K=512 in 8 chunks.
// A double-buffered (hi+lo per buffer), B single-buffered. 2 CTAs/SM.
// warp tile 32x64: rowg = wid>>2 (m32), colg = wid&3 (n64).
#define SM_E1      0          // 256 f
#define SM_E0      1024
#define SM_W3      2048
#define SM_G       3072       // 512 f -> 5120
#define SM_REPS    5120       // 64 f -> 5376
#define SM_PART    5376       // 4*64 f -> 6400
#define SM_A       8192       // 2 x (hi 8KB + lo 8KB) = 32 KB
#define A_STRIDE   16384
#define SM_B       40960      // hi 32KB + lo 32KB = 64 KB
#define SM_TOTAL   106496

__global__ __launch_bounds__(256, 2) void fused_mma(
    const float* __restrict__ rep, const float* __restrict__ b3,
    float* __restrict__ out)
{
    extern __shared__ __align__(1024) char smem[];
    const uint32_t sb = smem_u32(smem);
    const int b  = blockIdx.y;
    const int k0 = blockIdx.x * 64;
    const int t  = threadIdx.x;
    const int wid = t >> 5, lane = t & 31;
    const int rowg = wid >> 2, colg = wid & 3;

    // stage constants
    if (t < 256) {
        *(float*)(smem + SM_E1 + t * 4) = g_e1[t];
        *(float*)(smem + SM_E0 + t * 4) = g_e0[t];
        *(float*)(smem + SM_W3 + t * 4) = g_w3[t];
    }
    *(float*)(smem + SM_G + t * 4)         = g_G[(size_t)b * NH1 + t];
    *(float*)(smem + SM_G + (t + 256) * 4) = g_G[(size_t)b * NH1 + t + 256];
    if (t < 64) *(float*)(smem + SM_REPS + t * 4) = rep[(size_t)b * ND + k0 + t];
    __syncthreads();

    auto loadB = [&](int ch) {
        const int h0 = ch * 64;
#pragma unroll
        for (int i = 0; i < 8; i++) {
            int idx = t + i * 256;              // 0..2047
            int row = idx >> 3, seg = idx & 7;
            cpasync16(sb + SM_B + SWZ(row * 128 + seg * 16),
                      g_W2t_hi + (size_t)row * NH1 + h0 + seg * 8);
        }
#pragma unroll
        for (int i = 0; i < 8; i++) {
            int idx = t + i * 256;
            int row = idx >> 3, seg = idx & 7;
            cpasync16(sb + SM_B + 32768 + SWZ(row * 128 + seg * 16),
                      g_W2t_lo + (size_t)row * NH1 + h0 + seg * 8);
        }
        CP_COMMIT();
    };

    const int krow = t >> 2;          // 0..63
    const int hb   = (t & 3) * 16;
    const float rp = *(const float*)(smem + SM_REPS + krow * 4);

    auto buildA = [&](int ch) {
        const int h0 = ch * 64;
        uint32_t bufA = sb + SM_A + (ch & 1) * A_STRIDE;
#pragma unroll
        for (int half = 0; half < 2; half++) {
            uint32_t hv[4], lv[4];
#pragma unroll
            for (int j = 0; j < 2; j++) {
                int h4 = hb + half * 8 + j * 4;
                size_t goff = (size_t)(k0 + krow) * NH1 + h0 + h4;
                float4 wv = *(const float4*)(g_W1c + goff);
                float4 fv = *(const float4*)(g_F + goff);
                float4 gv = *(const float4*)(smem + SM_G + (h0 + h4) * 4);
                float u0 = fmaxf(gv.x + fv.x - rp * wv.x, 0.f);
                float u1 = fmaxf(gv.y + fv.y - rp * wv.y, 0.f);
                float u2 = fmaxf(gv.z + fv.z - rp * wv.z, 0.f);
                float u3 = fmaxf(gv.w + fv.w - rp * wv.w, 0.f);
                __nv_bfloat16 h0b = __float2bfloat16_rn(u0);
                __nv_bfloat16 h1b = __float2bfloat16_rn(u1);
                __nv_bfloat16 h2b = __float2bfloat16_rn(u2);
                __nv_bfloat16 h3b = __float2bfloat16_rn(u3);
                __nv_bfloat16 l0b = __float2bfloat16_rn(u0 - __bfloat162float(h0b));
                __nv_bfloat16 l1b = __float2bfloat16_rn(u1 - __bfloat162float(h1b));
                __nv_bfloat16 l2b = __float2bfloat16_rn(u2 - __bfloat162float(h2b));
                __nv_bfloat16 l3b = __float2bfloat16_rn(u3 - __bfloat162float(h3b));
                hv[2 * j]     = ((uint32_t)__bfloat16_as_ushort(h1b) << 16) | __bfloat16_as_ushort(h0b);
                hv[2 * j + 1] = ((uint32_t)__bfloat16_as_ushort(h3b) << 16) | __bfloat16_as_ushort(h2b);
                lv[2 * j]     = ((uint32_t)__bfloat16_as_ushort(l1b) << 16) | __bfloat16_as_ushort(l0b);
                lv[2 * j + 1] = ((uint32_t)__bfloat16_as_ushort(l3b) << 16) | __bfloat16_as_ushort(l2b);
            }
            uint32_t boff = SWZ(krow * 128 + (hb + half * 8) * 2);
            *(uint4*)(smem + SM_A + (ch & 1) * A_STRIDE + boff)        = make_uint4(hv[0], hv[1], hv[2], hv[3]);
            *(uint4*)(smem + SM_A + (ch & 1) * A_STRIDE + 8192 + boff) = make_uint4(lv[0], lv[1], lv[2], lv[3]);
        }
    };

    // ldmatrix address precompute
    uint32_t aOff[2]; int aX[2];
#pragma unroll
    for (int mt = 0; mt < 2; mt++) {
        int rowA = rowg * 32 + mt * 16 + (lane & 15);
        aOff[mt] = rowA * 128;
        aX[mt]   = (rowA & 7) << 4;
    }
    const int aCol = lane & 16;
    int bRow[4], bX[4];
#pragma unroll
    for (int bt = 0; bt < 4; bt++) {
        int rowB = colg * 64 + bt * 16 + (lane & 7) + ((lane & 16) >> 1);
        bRow[bt] = rowB * 128;
        bX[bt]   = (rowB & 7) << 4;
    }
    const int bCol = (lane & 8) << 1;

    float D[2][8][4];
#pragma unroll
    for (int mt = 0; mt < 2; mt++)
#pragma unroll
        for (int nt = 0; nt < 8; nt++)
#pragma unroll
            for (int j = 0; j < 4; j++) D[mt][nt][j] = 0.f;

    // prologue
    loadB(0);
    buildA(0);
    CP_WAIT0();
    __syncthreads();

#pragma unroll 1
    for (int ch = 0; ch < 8; ch++) {
        const uint32_t bufA = sb + SM_A + (ch & 1) * A_STRIDE;
        const uint32_t bufB = sb + SM_B;
        // ---- MMA(ch): 4 k-steps of 16; 3 terms ----
#pragma unroll
        for (int ks = 0; ks < 4; ks++) {
            const int cA = ks * 32 + aCol;
            const int cB = ks * 32 + bCol;
            uint32_t ah[2][4], al[2][4];
            ldsm_x4(ah[0], bufA + aOff[0] + (cA ^ aX[0]));
            ldsm_x4(ah[1], bufA + aOff[1] + (cA ^ aX[1]));
            ldsm_x4(al[0], bufA + 8192 + aOff[0] + (cA ^ aX[0]));
            ldsm_x4(al[1], bufA + 8192 + aOff[1] + (cA ^ aX[1]));
#pragma unroll
            for (int bth = 0; bth < 2; bth++) {
                uint32_t bh[2][4], bl[2][4];
#pragma unroll
                for (int bb = 0; bb < 2; bb++) {
                    int bt = 2 * bth + bb;
                    ldsm_x4(bh[bb], bufB + bRow[bt] + (cB ^ bX[bt]));
                }
#pragma unroll
                for (int mt = 0; mt < 2; mt++)
#pragma unroll
                    for (int bb = 0; bb < 2; bb++) {
                        int nt = 4 * bth + 2 * bb;
                        mma_bf16(D[mt][nt],     ah[mt], bh[bb]);
                        mma_bf16(D[mt][nt + 1], ah[mt], bh[bb] + 2);
                        mma_bf16(D[mt][nt],     al[mt], bh[bb]);
                        mma_bf16(D[mt][nt + 1], al[mt], bh[bb] + 2);
                    }
#pragma unroll
                for (int bb = 0; bb < 2; bb++) {
                    int bt = 2 * bth + bb;
                    ldsm_x4(bl[bb], bufB + 32768 + bRow[bt] + (cB ^ bX[bt]));
                }
#pragma unroll
                for (int mt = 0; mt < 2; mt++)
#pragma unroll
                    for (int bb = 0; bb < 2; bb++) {
                        int nt = 4 * bth + 2 * bb;
                        mma_bf16(D[mt][nt],     ah[mt], bl[bb]);
                        mma_bf16(D[mt][nt + 1], ah[mt], bl[bb] + 2);
                    }
            }
        }
        __syncthreads();                        // all warps done with B(ch) & A(ch)
        if (ch < 7) {
            loadB(ch + 1);                      // overwrite single B buffer (async)
            buildA(ch + 1);                     // into other A buffer, overlaps B load
            CP_WAIT0();
        }
        __syncthreads();
    }

    // ---- epilogue: BN2 + relu + W3 dot, reduce over o ----
#pragma unroll
    for (int mt = 0; mt < 2; mt++) {
        int r = rowg * 32 + mt * 16 + (lane >> 2);
        float s0 = 0.f, s1 = 0.f;
#pragma unroll
        for (int nt = 0; nt < 8; nt++) {
#pragma unroll
            for (int j = 0; j < 2; j++) {
                int o = colg * 64 + nt * 8 + 2 * (lane & 3) + j;
                float e1 = *(const float*)(smem + SM_E1 + o * 4);
                float e0 = *(const float*)(smem + SM_E0 + o * 4);
                float w3 = *(const float*)(smem + SM_W3 + o * 4);
                s0 = fmaf(fmaxf(fmaf(D[mt][nt][j],     e1, e0), 0.f), w3, s0);
                s1 = fmaf(fmaxf(fmaf(D[mt][nt][2 + j], e1, e0), 0.f), w3, s1);
            }
        }
        s0 += __shfl_xor_sync(0xffffffffu, s0, 1);
        s0 += __shfl_xor_sync(0xffffffffu, s0, 2);
        s1 += __shfl_xor_sync(0xffffffffu, s1, 1);
        s1 += __shfl_xor_sync(0xffffffffu, s1, 2);
        if ((lane & 3) == 0) {
            *(float*)(smem + SM_PART + (colg * 64 + r) * 4)     = s0;
            *(float*)(smem + SM_PART + (colg * 64 + r + 8) * 4) = s1;
        }
    }
    __syncthreads();
    if (t < 64) {
        float v = *(const float*)(smem + SM_PART + t * 4)
                + *(const float*)(smem + SM_PART + (64 + t) * 4)
                + *(const float*)(smem + SM_PART + (128 + t) * 4)
                + *(const float*)(smem + SM_PART + (192 + t) * 4);
        out[(size_t)b * ND + k0 + t] = v + b3[0];
    }
}

extern "C" void kernel_launch(void* const* d_in, const int* in_sizes, int n_in,
                              void* d_out, int out_size) {
    const float* rep   = (const float*)d_in[0];
    const float* emb   = (const float*)d_in[1];
    const float* W1    = (const float*)d_in[2];
    const float* b1    = (const float*)d_in[3];
    const float* g1    = (const float*)d_in[4];
    const float* beta1 = (const float*)d_in[5];
    const float* m1    = (const float*)d_in[6];
    const float* v1    = (const float*)d_in[7];
    const float* W2    = (const float*)d_in[8];
    const float* b2    = (const float*)d_in[9];
    const float* g2    = (const float*)d_in[10];
    const float* beta2 = (const float*)d_in[11];
    const float* m2    = (const float*)d_in[12];
    const float* v2    = (const float*)d_in[13];
    const float* W3    = (const float*)d_in[14];
    const float* b3    = (const float*)d_in[15];
    float* out = (float*)d_out;

    cudaFuncSetAttribute(fused_mma, cudaFuncAttributeMaxDynamicSharedMemorySize, SM_TOTAL);

    prep_consts<<<1, 512>>>(g1, beta1, m1, v1, b2, g2, beta2, m2, v2, W3);   // 0
    mega_prep<<<1024, 512>>>(rep, emb, W1, W2);                              // 1
    prep_G_fold<<<NB, 512>>>(b1);                                            // 2
    dim3 grid(ND / 64, NB);
    fused_mma<<<grid, 256, SM_TOTAL>>>(rep, b3, out);                        // 3 (profiled)
}